// round 1
// baseline (speedup 1.0000x reference)
#include <cuda_runtime.h>
#include <math.h>

#define BB 8
#define TT 1024
#define CC 1024
#define HH 16
#define HS 64
#define M_TOT (BB*TT)      // 8192
#define N_QKV (3*CC)       // 3072

// Scratch (static device globals — allocation-guard safe)
__device__ float g_q[BB*HH*TT*HS];     // [B,H,T,hs]
__device__ float g_k[BB*HH*TT*HS];
__device__ float g_v[BB*HH*TT*HS];
__device__ float g_att[BB*TT*CC];      // [B,T,C]

// ---------------------------------------------------------------------------
// SGEMM: C = A @ B + bias. 128x128 block tile, BK=8, 256 threads, 8x8/thread.
// QKV=true: scatter output into g_q/g_k/g_v in [B,H,T,hs] layout.
// QKV=false: plain store to Cout (row-major MxN). If A==nullptr, read g_att.
// All dims are multiples of the tile sizes for this problem (no bounds checks).
// ---------------------------------------------------------------------------
template<bool QKV>
__global__ __launch_bounds__(256)
void sgemm_kernel(const float* __restrict__ A, const float* __restrict__ Bm,
                  const float* __restrict__ bias, float* __restrict__ Cout,
                  int M, int N, int K)
{
    __shared__ float As[8][128];
    __shared__ float Bs[8][128];

    const float* Ap = A ? A : (const float*)g_att;

    int tid = threadIdx.x;
    int bm = blockIdx.y * 128;
    int bn = blockIdx.x * 128;

    // A loader: 128 rows x 8 k, 4 elems/thread (float4 along k)
    int a_row = tid >> 1;            // 0..127
    int a_k   = (tid & 1) * 4;       // 0 or 4
    // B loader: 8 k x 128 n, float4 along n
    int b_k = tid >> 5;              // 0..7
    int b_n = (tid & 31) * 4;        // 0..124

    int ty = tid >> 4;               // 0..15
    int tx = tid & 15;               // 0..15

    float acc[8][8];
#pragma unroll
    for (int i = 0; i < 8; i++)
#pragma unroll
        for (int j = 0; j < 8; j++) acc[i][j] = 0.f;

    const float* Aptr = Ap + (size_t)(bm + a_row) * K + a_k;
    const float* Bptr = Bm + (size_t)b_k * N + bn + b_n;

    for (int k0 = 0; k0 < K; k0 += 8) {
        float4 av = *(const float4*)(Aptr + k0);
        As[a_k + 0][a_row] = av.x;
        As[a_k + 1][a_row] = av.y;
        As[a_k + 2][a_row] = av.z;
        As[a_k + 3][a_row] = av.w;
        float4 bv = *(const float4*)(Bptr + (size_t)k0 * N);
        *(float4*)&Bs[b_k][b_n] = bv;
        __syncthreads();

#pragma unroll
        for (int k = 0; k < 8; k++) {
            float4 ra0 = *(const float4*)&As[k][ty * 8];
            float4 ra1 = *(const float4*)&As[k][ty * 8 + 4];
            float4 rb0 = *(const float4*)&Bs[k][tx * 8];
            float4 rb1 = *(const float4*)&Bs[k][tx * 8 + 4];
            float ra[8] = {ra0.x, ra0.y, ra0.z, ra0.w, ra1.x, ra1.y, ra1.z, ra1.w};
            float rb[8] = {rb0.x, rb0.y, rb0.z, rb0.w, rb1.x, rb1.y, rb1.z, rb1.w};
#pragma unroll
            for (int i = 0; i < 8; i++)
#pragma unroll
                for (int j = 0; j < 8; j++)
                    acc[i][j] += ra[i] * rb[j];
        }
        __syncthreads();
    }

    // Epilogue
#pragma unroll
    for (int i = 0; i < 8; i++) {
        int m = bm + ty * 8 + i;
#pragma unroll
        for (int j = 0; j < 8; j++) {
            int n = bn + tx * 8 + j;
            float v = acc[i][j] + bias[n];
            if (QKV) {
                int b = m / TT, t = m % TT;
                int sel = n / CC, c = n % CC;
                int h = c / HS, d = c % HS;
                float* dst = (sel == 0) ? g_q : ((sel == 1) ? g_k : g_v);
                dst[(((size_t)b * HH + h) * TT + t) * HS + d] = v;
            } else {
                Cout[(size_t)m * N + n] = v;
            }
        }
    }
}

// ---------------------------------------------------------------------------
// Flash attention (fp32, causal). Q tile = 64 rows, KV tile = 32 rows.
// Block: 256 threads. grid = (T/64, H, B). Output to g_att [B,T,C].
// ---------------------------------------------------------------------------
__global__ __launch_bounds__(256)
void attn_kernel()
{
    __shared__ float Qs[64][65];
    __shared__ float Ks[32][65];
    __shared__ float Vs[32][65];
    __shared__ float Ss[64][33];
    __shared__ float m_s[64], l_s[64], fac[64];

    int tid = threadIdx.x;
    int qt = blockIdx.x;   // q tile 0..15
    int h  = blockIdx.y;
    int b  = blockIdx.z;

    const float* Qp = g_q + (((size_t)b * HH + h) * TT) * HS;
    const float* Kp = g_k + (((size_t)b * HH + h) * TT) * HS;
    const float* Vp = g_v + (((size_t)b * HH + h) * TT) * HS;

    // Load Q tile 64x64 (16 elems/thread)
    {
        int row = tid >> 2;
        int d0  = (tid & 3) * 16;
#pragma unroll
        for (int u = 0; u < 4; u++) {
            float4 v = *(const float4*)(Qp + (size_t)(qt * 64 + row) * HS + d0 + u * 4);
            Qs[row][d0 + u * 4 + 0] = v.x;
            Qs[row][d0 + u * 4 + 1] = v.y;
            Qs[row][d0 + u * 4 + 2] = v.z;
            Qs[row][d0 + u * 4 + 3] = v.w;
        }
    }
    if (tid < 64) { m_s[tid] = -INFINITY; l_s[tid] = 0.f; }

    int tr = tid >> 4, tc = tid & 15;   // S: rows tr*4.., cols tc*2..
    int ty = tr,       tx = tc;         // O: rows ty*4.., cols tx*4..

    float acc[4][4];
#pragma unroll
    for (int i = 0; i < 4; i++)
#pragma unroll
        for (int j = 0; j < 4; j++) acc[i][j] = 0.f;

    __syncthreads();

    int jmax = 2 * qt + 1;   // last KV tile overlapping causal range
    for (int jt = 0; jt <= jmax; jt++) {
        // Load K,V tiles 32x64 each (8 elems/thread each)
        {
            int kk = tid >> 3;
            int d0 = (tid & 7) * 8;
            const float* kr = Kp + (size_t)(jt * 32 + kk) * HS + d0;
            const float* vr = Vp + (size_t)(jt * 32 + kk) * HS + d0;
            float4 k0 = *(const float4*)(kr);
            float4 k1 = *(const float4*)(kr + 4);
            float4 v0 = *(const float4*)(vr);
            float4 v1 = *(const float4*)(vr + 4);
            Ks[kk][d0+0]=k0.x; Ks[kk][d0+1]=k0.y; Ks[kk][d0+2]=k0.z; Ks[kk][d0+3]=k0.w;
            Ks[kk][d0+4]=k1.x; Ks[kk][d0+5]=k1.y; Ks[kk][d0+6]=k1.z; Ks[kk][d0+7]=k1.w;
            Vs[kk][d0+0]=v0.x; Vs[kk][d0+1]=v0.y; Vs[kk][d0+2]=v0.z; Vs[kk][d0+3]=v0.w;
            Vs[kk][d0+4]=v1.x; Vs[kk][d0+5]=v1.y; Vs[kk][d0+6]=v1.z; Vs[kk][d0+7]=v1.w;
        }
        __syncthreads();

        // S = Q K^T  (4x2 per thread)
        float s[4][2];
#pragma unroll
        for (int i = 0; i < 4; i++)
#pragma unroll
            for (int j = 0; j < 2; j++) s[i][j] = 0.f;

#pragma unroll 8
        for (int d = 0; d < 64; d++) {
            float qv0 = Qs[tr*4+0][d];
            float qv1 = Qs[tr*4+1][d];
            float qv2 = Qs[tr*4+2][d];
            float qv3 = Qs[tr*4+3][d];
            float kv0 = Ks[tc*2+0][d];
            float kv1 = Ks[tc*2+1][d];
            s[0][0] += qv0*kv0; s[0][1] += qv0*kv1;
            s[1][0] += qv1*kv0; s[1][1] += qv1*kv1;
            s[2][0] += qv2*kv0; s[2][1] += qv2*kv1;
            s[3][0] += qv3*kv0; s[3][1] += qv3*kv1;
        }

        // Scale + causal mask + stage to shared
#pragma unroll
        for (int i = 0; i < 4; i++) {
            int grow = qt * 64 + tr * 4 + i;
#pragma unroll
            for (int j = 0; j < 2; j++) {
                int gcol = jt * 32 + tc * 2 + j;
                float val = s[i][j] * 0.125f;   // hs^-0.5 = 1/8
                if (gcol > grow) val = -INFINITY;
                Ss[tr*4+i][tc*2+j] = val;
            }
        }
        __syncthreads();

        // Online softmax row pass (one thread per row)
        if (tid < 64) {
            int r = tid;
            float mold = m_s[r];
            float mx = mold;
#pragma unroll 8
            for (int k = 0; k < 32; k++) mx = fmaxf(mx, Ss[r][k]);
            float f = __expf(mold - mx);     // 0 when mold == -inf
            float sum = 0.f;
#pragma unroll 8
            for (int k = 0; k < 32; k++) {
                float p = __expf(Ss[r][k] - mx);
                Ss[r][k] = p;
                sum += p;
            }
            m_s[r] = mx;
            l_s[r] = l_s[r] * f + sum;
            fac[r] = f;
        }
        __syncthreads();

        // O = O * fac + P @ V  (4x4 per thread)
        float f0 = fac[ty*4+0], f1 = fac[ty*4+1], f2 = fac[ty*4+2], f3 = fac[ty*4+3];
#pragma unroll
        for (int j = 0; j < 4; j++) {
            acc[0][j] *= f0; acc[1][j] *= f1; acc[2][j] *= f2; acc[3][j] *= f3;
        }
#pragma unroll 8
        for (int k = 0; k < 32; k++) {
            float p0 = Ss[ty*4+0][k];
            float p1 = Ss[ty*4+1][k];
            float p2 = Ss[ty*4+2][k];
            float p3 = Ss[ty*4+3][k];
            float v0 = Vs[k][tx*4+0];
            float v1 = Vs[k][tx*4+1];
            float v2 = Vs[k][tx*4+2];
            float v3 = Vs[k][tx*4+3];
            acc[0][0]+=p0*v0; acc[0][1]+=p0*v1; acc[0][2]+=p0*v2; acc[0][3]+=p0*v3;
            acc[1][0]+=p1*v0; acc[1][1]+=p1*v1; acc[1][2]+=p1*v2; acc[1][3]+=p1*v3;
            acc[2][0]+=p2*v0; acc[2][1]+=p2*v1; acc[2][2]+=p2*v2; acc[2][3]+=p2*v3;
            acc[3][0]+=p3*v0; acc[3][1]+=p3*v1; acc[3][2]+=p3*v2; acc[3][3]+=p3*v3;
        }
        __syncthreads();   // protect Ks/Vs/Ss for next tile
    }

    // Final normalize + store to g_att [B,T,C] (head h occupies cols h*64..)
#pragma unroll
    for (int i = 0; i < 4; i++) {
        int t = qt * 64 + ty * 4 + i;
        float inv_l = 1.0f / l_s[ty*4+i];
#pragma unroll
        for (int j = 0; j < 4; j++) {
            g_att[((size_t)b * TT + t) * CC + h * HS + tx * 4 + j] = acc[i][j] * inv_l;
        }
    }
}

// ---------------------------------------------------------------------------
extern "C" void kernel_launch(void* const* d_in, const int* in_sizes, int n_in,
                              void* d_out, int out_size)
{
    (void)in_sizes; (void)n_in; (void)out_size;
    const float* x     = (const float*)d_in[0];
    const float* Wqkv  = (const float*)d_in[1];
    const float* bqkv  = (const float*)d_in[2];
    const float* Wproj = (const float*)d_in[3];
    const float* bproj = (const float*)d_in[4];
    float* out = (float*)d_out;

    // 1) QKV GEMM: [8192,1024] @ [1024,3072], scatter to g_q/g_k/g_v
    dim3 g1(N_QKV / 128, M_TOT / 128);
    sgemm_kernel<true><<<g1, 256>>>(x, Wqkv, bqkv, nullptr, M_TOT, N_QKV, CC);

    // 2) Causal flash attention -> g_att [B,T,C]
    dim3 ga(TT / 64, HH, BB);
    attn_kernel<<<ga, 256>>>();

    // 3) Output projection: g_att @ Wproj + bproj -> out
    dim3 g2(CC / 128, M_TOT / 128);
    sgemm_kernel<false><<<g2, 256>>>(nullptr, Wproj, bproj, out, M_TOT, CC, CC);
}

// round 3
// speedup vs baseline: 1.9115x; 1.9115x over previous
#include <cuda_runtime.h>
#include <cuda_bf16.h>
#include <math.h>
#include <stdint.h>

#define BB 8
#define TT 1024
#define CC 1024
#define HH 16
#define HS 64
#define M_TOT (BB*TT)      // 8192
#define KK 1024
#define N_QKV (3*CC)       // 3072

// ---------------------------------------------------------------------------
// Scratch (__device__ globals — allocation-guard safe)
// ---------------------------------------------------------------------------
__device__ __nv_bfloat16 g_xhi[(size_t)M_TOT*KK];
__device__ __nv_bfloat16 g_xlo[(size_t)M_TOT*KK];
__device__ __nv_bfloat16 g_wqT_hi[(size_t)N_QKV*KK];
__device__ __nv_bfloat16 g_wqT_lo[(size_t)N_QKV*KK];
__device__ __nv_bfloat16 g_wpT_hi[(size_t)CC*KK];
__device__ __nv_bfloat16 g_wpT_lo[(size_t)CC*KK];
__device__ float g_q[(size_t)BB*HH*TT*HS];
__device__ float g_k[(size_t)BB*HH*TT*HS];
__device__ float g_v[(size_t)BB*HH*TT*HS];
__device__ __nv_bfloat16 g_atthi[(size_t)M_TOT*CC];
__device__ __nv_bfloat16 g_attlo[(size_t)M_TOT*CC];

// ---------------------------------------------------------------------------
// helpers
// ---------------------------------------------------------------------------
__device__ __forceinline__ uint32_t smem_u32(const void* p) {
    uint32_t a;
    asm("{ .reg .u64 t; cvta.to.shared.u64 t, %1; cvt.u32.u64 %0, t; }" : "=r"(a) : "l"(p));
    return a;
}
__device__ __forceinline__ void cp16(uint32_t dst, const void* src) {
    asm volatile("cp.async.cg.shared.global [%0], [%1], 16;" :: "r"(dst), "l"(src));
}
#define CP_COMMIT() asm volatile("cp.async.commit_group;" ::: "memory")
#define CP_WAIT(n)  asm volatile("cp.async.wait_group %0;" :: "n"(n) : "memory")

__device__ __forceinline__ void ldsm_x4(uint32_t* r, uint32_t addr) {
    asm volatile("ldmatrix.sync.aligned.m8n8.x4.shared.b16 {%0,%1,%2,%3}, [%4];"
        : "=r"(r[0]), "=r"(r[1]), "=r"(r[2]), "=r"(r[3]) : "r"(addr));
}
__device__ __forceinline__ void mma_bf16(float* d, const uint32_t* a,
                                         uint32_t b0, uint32_t b1) {
    asm volatile(
        "mma.sync.aligned.m16n8k16.row.col.f32.bf16.bf16.f32 "
        "{%0,%1,%2,%3},{%4,%5,%6,%7},{%8,%9},{%0,%1,%2,%3};"
        : "+f"(d[0]), "+f"(d[1]), "+f"(d[2]), "+f"(d[3])
        : "r"(a[0]), "r"(a[1]), "r"(a[2]), "r"(a[3]), "r"(b0), "r"(b1));
}

// ---------------------------------------------------------------------------
// Preprocessing: x -> bf16 hi/lo
// ---------------------------------------------------------------------------
__global__ __launch_bounds__(256) void convert_x_kernel(const float* __restrict__ x)
{
    int i = blockIdx.x * 256 + threadIdx.x;
    float4 v = ((const float4*)x)[i];
    __nv_bfloat162 h0, h1, l0, l1;
    h0.x = __float2bfloat16(v.x); h0.y = __float2bfloat16(v.y);
    h1.x = __float2bfloat16(v.z); h1.y = __float2bfloat16(v.w);
    l0.x = __float2bfloat16(v.x - __bfloat162float(h0.x));
    l0.y = __float2bfloat16(v.y - __bfloat162float(h0.y));
    l1.x = __float2bfloat16(v.z - __bfloat162float(h1.x));
    l1.y = __float2bfloat16(v.w - __bfloat162float(h1.y));
    ((__nv_bfloat162*)g_xhi)[2*i]   = h0;
    ((__nv_bfloat162*)g_xhi)[2*i+1] = h1;
    ((__nv_bfloat162*)g_xlo)[2*i]   = l0;
    ((__nv_bfloat162*)g_xlo)[2*i+1] = l1;
}

// ---------------------------------------------------------------------------
// W [K,N] fp32 -> W^T [N,K] bf16 hi/lo.  SEL 0: qkv, 1: proj
// ---------------------------------------------------------------------------
template<int SEL>
__global__ __launch_bounds__(256) void transpose_w_kernel(const float* __restrict__ W, int N)
{
    __shared__ float tile[32][33];
    int tx = threadIdx.x, ty = threadIdx.y;          // (32, 8)
    int n0 = blockIdx.x * 32;
    int k0 = blockIdx.y * 32;
#pragma unroll
    for (int j = 0; j < 4; j++)
        tile[ty + j*8][tx] = W[(size_t)(k0 + ty + j*8) * N + n0 + tx];
    __syncthreads();
    __nv_bfloat16* Th = SEL ? g_wpT_hi : g_wqT_hi;
    __nv_bfloat16* Tl = SEL ? g_wpT_lo : g_wqT_lo;
#pragma unroll
    for (int j = 0; j < 4; j++) {
        float v = tile[tx][ty + j*8];
        __nv_bfloat16 h = __float2bfloat16(v);
        size_t o = (size_t)(n0 + ty + j*8) * KK + k0 + tx;
        Th[o] = h;
        Tl[o] = __float2bfloat16(v - __bfloat162float(h));
    }
}

// ---------------------------------------------------------------------------
// HMMA GEMM: D[M,N] = A @ W^T' + bias, 3-pass bf16 hi/lo (Ah*Bh + Ah*Bl + Al*Bh)
// 128x128 CTA tile, BK=32, 256 threads (8 warps, 2x4), warp tile 64x32.
// MODE 0: A=g_x*, B=g_wqT*, scatter into g_q/g_k/g_v.  MODE 1: A=g_att*, B=g_wpT*.
// ---------------------------------------------------------------------------
#define SUB_BYTES 10240        // 128 rows x 80B (32 bf16 + 16B pad)
#define STAGE_BYTES (4*SUB_BYTES)   // Ahi, Alo, Bhi, Blo
#define GEMM_SMEM (2*STAGE_BYTES)   // 81920

template<int MODE>
__global__ __launch_bounds__(256, 2)
void gemm_tc(const float* __restrict__ bias, float* __restrict__ out)
{
    extern __shared__ char smem[];
    const uint32_t sbase = smem_u32(smem);

    const int tid = threadIdx.x;
    const int wid = tid >> 5;
    const int lane = tid & 31;
    const int wm = wid >> 2;          // 0..1
    const int wn = wid & 3;           // 0..3
    const int m0 = blockIdx.y * 128;
    const int n0 = blockIdx.x * 128;

    const __nv_bfloat16* Ahi = MODE ? g_atthi : g_xhi;
    const __nv_bfloat16* Alo = MODE ? g_attlo : g_xlo;
    const __nv_bfloat16* Bhi = MODE ? g_wpT_hi : g_wqT_hi;
    const __nv_bfloat16* Blo = MODE ? g_wpT_lo : g_wqT_lo;

    const __nv_bfloat16* gsrc[4] = {
        Ahi + (size_t)m0 * KK, Alo + (size_t)m0 * KK,
        Bhi + (size_t)n0 * KK, Blo + (size_t)n0 * KK };

    // per-thread cp.async pattern: 2048 chunks/stage, 8 per thread
    // id = i*256+tid ; sub = id>>9 ; row = (id&511)>>2 ; c = id&3
    auto load_stage = [&](int s) {
        const int k0 = s * 32;
        const uint32_t sb = sbase + (s & 1) * STAGE_BYTES;
#pragma unroll
        for (int i = 0; i < 8; i++) {
            int id = i * 256 + tid;
            int sub = id >> 9;
            int row = (id & 511) >> 2;
            int c = id & 3;
            const void* src = gsrc[sub] + (size_t)row * KK + k0 + c * 8;
            cp16(sb + sub * SUB_BYTES + row * 80 + c * 16, src);
        }
        CP_COMMIT();
    };

    // ldmatrix lane offset (shared by A and B tiles)
    const uint32_t laneOff = (lane & 15) * 80 + (lane >> 4) * 16;

    float acc[4][4][4];
#pragma unroll
    for (int i = 0; i < 4; i++)
#pragma unroll
        for (int j = 0; j < 4; j++)
#pragma unroll
            for (int e = 0; e < 4; e++) acc[i][j][e] = 0.f;

    load_stage(0);

    for (int s = 0; s < 32; s++) {
        if (s + 1 < 32) { load_stage(s + 1); CP_WAIT(1); }
        else            { CP_WAIT(0); }
        __syncthreads();

        const uint32_t sb = sbase + (s & 1) * STAGE_BYTES;
        const uint32_t aB = sb + (wm * 64) * 80 + laneOff;                    // Ahi
        const uint32_t bB = sb + 2 * SUB_BYTES + (wn * 32) * 80 + laneOff;    // Bhi

#pragma unroll
        for (int ks = 0; ks < 2; ks++) {
            const uint32_t ko = ks * 32;
            uint32_t af[16], bh[8], bl[8];
#pragma unroll
            for (int mi = 0; mi < 4; mi++) ldsm_x4(&af[mi*4], aB + mi * 16 * 80 + ko);
#pragma unroll
            for (int np = 0; np < 2; np++) ldsm_x4(&bh[np*4], bB + np * 16 * 80 + ko);
#pragma unroll
            for (int np = 0; np < 2; np++) ldsm_x4(&bl[np*4], bB + SUB_BYTES + np * 16 * 80 + ko);

            // pass 1: Ahi * Bhi ; pass 2: Ahi * Blo
#pragma unroll
            for (int mi = 0; mi < 4; mi++)
#pragma unroll
                for (int ni = 0; ni < 4; ni++) {
                    int np = ni >> 1, h = ni & 1;
                    mma_bf16(acc[mi][ni], &af[mi*4], bh[np*4+h], bh[np*4+2+h]);
                }
#pragma unroll
            for (int mi = 0; mi < 4; mi++)
#pragma unroll
                for (int ni = 0; ni < 4; ni++) {
                    int np = ni >> 1, h = ni & 1;
                    mma_bf16(acc[mi][ni], &af[mi*4], bl[np*4+h], bl[np*4+2+h]);
                }
            // pass 3: Alo * Bhi (reuse af regs)
#pragma unroll
            for (int mi = 0; mi < 4; mi++) ldsm_x4(&af[mi*4], aB + SUB_BYTES + mi * 16 * 80 + ko);
#pragma unroll
            for (int mi = 0; mi < 4; mi++)
#pragma unroll
                for (int ni = 0; ni < 4; ni++) {
                    int np = ni >> 1, h = ni & 1;
                    mma_bf16(acc[mi][ni], &af[mi*4], bh[np*4+h], bh[np*4+2+h]);
                }
        }
        __syncthreads();
    }

    // ---- epilogue: accums -> smem (fp32, padded), then coalesced stores ----
    float* Ssm = (float*)smem;          // [128][132]
#pragma unroll
    for (int mi = 0; mi < 4; mi++) {
        int m = wm * 64 + mi * 16 + (lane >> 2);
#pragma unroll
        for (int ni = 0; ni < 4; ni++) {
            int n = wn * 32 + ni * 8 + 2 * (lane & 3);
            Ssm[m * 132 + n]           = acc[mi][ni][0];
            Ssm[m * 132 + n + 1]       = acc[mi][ni][1];
            Ssm[(m + 8) * 132 + n]     = acc[mi][ni][2];
            Ssm[(m + 8) * 132 + n + 1] = acc[mi][ni][3];
        }
    }
    __syncthreads();

#pragma unroll 4
    for (int it = 0; it < 16; it++) {
        int f4 = it * 256 + tid;
        int row = f4 >> 5;
        int nl = (f4 & 31) * 4;
        float4 v = *(const float4*)&Ssm[row * 132 + nl];
        float4 bv = *(const float4*)&bias[n0 + nl];
        v.x += bv.x; v.y += bv.y; v.z += bv.z; v.w += bv.w;
        int gm = m0 + row;
        int gn = n0 + nl;
        if (MODE) {
            *(float4*)&out[(size_t)gm * CC + gn] = v;
        } else {
            int b = gm >> 10, t = gm & 1023;
            int sel = gn >> 10, c = gn & 1023;
            int h = c >> 6, d = c & 63;
            float* dst = (sel == 0) ? g_q : ((sel == 1) ? g_k : g_v);
            *(float4*)&dst[(((size_t)b * HH + h) * TT + t) * HS + d] = v;
        }
    }
}

// ---------------------------------------------------------------------------
// Flash attention (fp32, causal). Epilogue emits bf16 hi/lo into g_att*.
// ---------------------------------------------------------------------------
__global__ __launch_bounds__(256)
void attn_kernel()
{
    __shared__ float Qs[64][65];
    __shared__ float Ks[32][65];
    __shared__ float Vs[32][65];
    __shared__ float Ss[64][33];
    __shared__ float m_s[64], l_s[64], fac[64];

    int tid = threadIdx.x;
    int qt = blockIdx.x;
    int h  = blockIdx.y;
    int b  = blockIdx.z;

    const float* Qp = g_q + (((size_t)b * HH + h) * TT) * HS;
    const float* Kp = g_k + (((size_t)b * HH + h) * TT) * HS;
    const float* Vp = g_v + (((size_t)b * HH + h) * TT) * HS;

    {
        int row = tid >> 2;
        int d0  = (tid & 3) * 16;
#pragma unroll
        for (int u = 0; u < 4; u++) {
            float4 v = *(const float4*)(Qp + (size_t)(qt * 64 + row) * HS + d0 + u * 4);
            Qs[row][d0 + u*4 + 0] = v.x; Qs[row][d0 + u*4 + 1] = v.y;
            Qs[row][d0 + u*4 + 2] = v.z; Qs[row][d0 + u*4 + 3] = v.w;
        }
    }
    if (tid < 64) { m_s[tid] = -INFINITY; l_s[tid] = 0.f; }

    int tr = tid >> 4, tc = tid & 15;
    int ty = tr,       tx = tc;

    float acc[4][4];
#pragma unroll
    for (int i = 0; i < 4; i++)
#pragma unroll
        for (int j = 0; j < 4; j++) acc[i][j] = 0.f;

    __syncthreads();

    int jmax = 2 * qt + 1;
    for (int jt = 0; jt <= jmax; jt++) {
        {
            int kk = tid >> 3;
            int d0 = (tid & 7) * 8;
            const float* kr = Kp + (size_t)(jt * 32 + kk) * HS + d0;
            const float* vr = Vp + (size_t)(jt * 32 + kk) * HS + d0;
            float4 k0 = *(const float4*)(kr);
            float4 k1 = *(const float4*)(kr + 4);
            float4 v0 = *(const float4*)(vr);
            float4 v1 = *(const float4*)(vr + 4);
            Ks[kk][d0+0]=k0.x; Ks[kk][d0+1]=k0.y; Ks[kk][d0+2]=k0.z; Ks[kk][d0+3]=k0.w;
            Ks[kk][d0+4]=k1.x; Ks[kk][d0+5]=k1.y; Ks[kk][d0+6]=k1.z; Ks[kk][d0+7]=k1.w;
            Vs[kk][d0+0]=v0.x; Vs[kk][d0+1]=v0.y; Vs[kk][d0+2]=v0.z; Vs[kk][d0+3]=v0.w;
            Vs[kk][d0+4]=v1.x; Vs[kk][d0+5]=v1.y; Vs[kk][d0+6]=v1.z; Vs[kk][d0+7]=v1.w;
        }
        __syncthreads();

        float s[4][2];
#pragma unroll
        for (int i = 0; i < 4; i++)
#pragma unroll
            for (int j = 0; j < 2; j++) s[i][j] = 0.f;

#pragma unroll 8
        for (int d = 0; d < 64; d++) {
            float qv0 = Qs[tr*4+0][d];
            float qv1 = Qs[tr*4+1][d];
            float qv2 = Qs[tr*4+2][d];
            float qv3 = Qs[tr*4+3][d];
            float kv0 = Ks[tc*2+0][d];
            float kv1 = Ks[tc*2+1][d];
            s[0][0] += qv0*kv0; s[0][1] += qv0*kv1;
            s[1][0] += qv1*kv0; s[1][1] += qv1*kv1;
            s[2][0] += qv2*kv0; s[2][1] += qv2*kv1;
            s[3][0] += qv3*kv0; s[3][1] += qv3*kv1;
        }

#pragma unroll
        for (int i = 0; i < 4; i++) {
            int grow = qt * 64 + tr * 4 + i;
#pragma unroll
            for (int j = 0; j < 2; j++) {
                int gcol = jt * 32 + tc * 2 + j;
                float val = s[i][j] * 0.125f;
                if (gcol > grow) val = -INFINITY;
                Ss[tr*4+i][tc*2+j] = val;
            }
        }
        __syncthreads();

        if (tid < 64) {
            int r = tid;
            float mold = m_s[r];
            float mx = mold;
#pragma unroll 8
            for (int k = 0; k < 32; k++) mx = fmaxf(mx, Ss[r][k]);
            float f = __expf(mold - mx);
            float sum = 0.f;
#pragma unroll 8
            for (int k = 0; k < 32; k++) {
                float p = __expf(Ss[r][k] - mx);
                Ss[r][k] = p;
                sum += p;
            }
            m_s[r] = mx;
            l_s[r] = l_s[r] * f + sum;
            fac[r] = f;
        }
        __syncthreads();

        float f0 = fac[ty*4+0], f1 = fac[ty*4+1], f2 = fac[ty*4+2], f3 = fac[ty*4+3];
#pragma unroll
        for (int j = 0; j < 4; j++) {
            acc[0][j] *= f0; acc[1][j] *= f1; acc[2][j] *= f2; acc[3][j] *= f3;
        }
#pragma unroll 8
        for (int k = 0; k < 32; k++) {
            float p0 = Ss[ty*4+0][k];
            float p1 = Ss[ty*4+1][k];
            float p2 = Ss[ty*4+2][k];
            float p3 = Ss[ty*4+3][k];
            float v0 = Vs[k][tx*4+0];
            float v1 = Vs[k][tx*4+1];
            float v2 = Vs[k][tx*4+2];
            float v3 = Vs[k][tx*4+3];
            acc[0][0]+=p0*v0; acc[0][1]+=p0*v1; acc[0][2]+=p0*v2; acc[0][3]+=p0*v3;
            acc[1][0]+=p1*v0; acc[1][1]+=p1*v1; acc[1][2]+=p1*v2; acc[1][3]+=p1*v3;
            acc[2][0]+=p2*v0; acc[2][1]+=p2*v1; acc[2][2]+=p2*v2; acc[2][3]+=p2*v3;
            acc[3][0]+=p3*v0; acc[3][1]+=p3*v1; acc[3][2]+=p3*v2; acc[3][3]+=p3*v3;
        }
        __syncthreads();
    }

#pragma unroll
    for (int i = 0; i < 4; i++) {
        int t = qt * 64 + ty * 4 + i;
        float inv_l = 1.0f / l_s[ty*4+i];
        size_t rowb = ((size_t)b * TT + t) * CC + h * HS;
#pragma unroll
        for (int j = 0; j < 4; j++) {
            float o = acc[i][j] * inv_l;
            __nv_bfloat16 hh = __float2bfloat16(o);
            size_t idx = rowb + tx * 4 + j;
            g_atthi[idx] = hh;
            g_attlo[idx] = __float2bfloat16(o - __bfloat162float(hh));
        }
    }
}

// ---------------------------------------------------------------------------
extern "C" void kernel_launch(void* const* d_in, const int* in_sizes, int n_in,
                              void* d_out, int out_size)
{
    (void)in_sizes; (void)n_in; (void)out_size;
    const float* x     = (const float*)d_in[0];
    const float* Wqkv  = (const float*)d_in[1];
    const float* bqkv  = (const float*)d_in[2];
    const float* Wproj = (const float*)d_in[3];
    const float* bproj = (const float*)d_in[4];
    float* out = (float*)d_out;

    cudaFuncSetAttribute(gemm_tc<0>, cudaFuncAttributeMaxDynamicSharedMemorySize, GEMM_SMEM);
    cudaFuncSetAttribute(gemm_tc<1>, cudaFuncAttributeMaxDynamicSharedMemorySize, GEMM_SMEM);

    // preprocessing
    convert_x_kernel<<<(M_TOT * KK / 4) / 256, 256>>>(x);
    transpose_w_kernel<0><<<dim3(N_QKV / 32, KK / 32), dim3(32, 8)>>>(Wqkv, N_QKV);
    transpose_w_kernel<1><<<dim3(CC / 32, KK / 32), dim3(32, 8)>>>(Wproj, CC);

    // QKV GEMM (HMMA bf16x3)
    gemm_tc<0><<<dim3(N_QKV / 128, M_TOT / 128), 256, GEMM_SMEM>>>(bqkv, nullptr);

    // causal flash attention (fp32)
    attn_kernel<<<dim3(TT / 64, HH, BB), 256>>>();

    // output projection (HMMA bf16x3)
    gemm_tc<1><<<dim3(CC / 128, M_TOT / 128), 256, GEMM_SMEM>>>(bproj, out);
}

// round 4
// speedup vs baseline: 3.0610x; 1.6013x over previous
#include <cuda_runtime.h>
#include <cuda_bf16.h>
#include <math.h>
#include <stdint.h>

#define BB 8
#define TT 1024
#define CC 1024
#define HH 16
#define HS 64
#define M_TOT (BB*TT)      // 8192
#define KK 1024
#define N_QKV (3*CC)       // 3072

// ---------------------------------------------------------------------------
// Scratch (__device__ globals — allocation-guard safe)
// ---------------------------------------------------------------------------
__device__ __nv_bfloat16 g_xhi[(size_t)M_TOT*KK];
__device__ __nv_bfloat16 g_xlo[(size_t)M_TOT*KK];
__device__ __nv_bfloat16 g_wqT_hi[(size_t)N_QKV*KK];
__device__ __nv_bfloat16 g_wqT_lo[(size_t)N_QKV*KK];
__device__ __nv_bfloat16 g_wpT_hi[(size_t)CC*KK];
__device__ __nv_bfloat16 g_wpT_lo[(size_t)CC*KK];
__device__ __nv_bfloat16 g_qhi[(size_t)BB*HH*TT*HS];
__device__ __nv_bfloat16 g_qlo[(size_t)BB*HH*TT*HS];
__device__ __nv_bfloat16 g_khi[(size_t)BB*HH*TT*HS];
__device__ __nv_bfloat16 g_klo[(size_t)BB*HH*TT*HS];
__device__ __nv_bfloat16 g_vhi[(size_t)BB*HH*TT*HS];
__device__ __nv_bfloat16 g_vlo[(size_t)BB*HH*TT*HS];
__device__ __nv_bfloat16 g_atthi[(size_t)M_TOT*CC];
__device__ __nv_bfloat16 g_attlo[(size_t)M_TOT*CC];

// ---------------------------------------------------------------------------
// helpers
// ---------------------------------------------------------------------------
__device__ __forceinline__ uint32_t smem_u32(const void* p) {
    uint32_t a;
    asm("{ .reg .u64 t; cvta.to.shared.u64 t, %1; cvt.u32.u64 %0, t; }" : "=r"(a) : "l"(p));
    return a;
}
__device__ __forceinline__ void cp16(uint32_t dst, const void* src) {
    asm volatile("cp.async.cg.shared.global [%0], [%1], 16;" :: "r"(dst), "l"(src));
}
#define CP_COMMIT() asm volatile("cp.async.commit_group;" ::: "memory")
#define CP_WAIT(n)  asm volatile("cp.async.wait_group %0;" :: "n"(n) : "memory")

__device__ __forceinline__ void ldsm_x4(uint32_t* r, uint32_t addr) {
    asm volatile("ldmatrix.sync.aligned.m8n8.x4.shared.b16 {%0,%1,%2,%3}, [%4];"
        : "=r"(r[0]), "=r"(r[1]), "=r"(r[2]), "=r"(r[3]) : "r"(addr));
}
__device__ __forceinline__ void ldsm_x4t(uint32_t* r, uint32_t addr) {
    asm volatile("ldmatrix.sync.aligned.m8n8.x4.trans.shared.b16 {%0,%1,%2,%3}, [%4];"
        : "=r"(r[0]), "=r"(r[1]), "=r"(r[2]), "=r"(r[3]) : "r"(addr));
}
__device__ __forceinline__ void mma_bf16(float* d, const uint32_t* a,
                                         uint32_t b0, uint32_t b1) {
    asm volatile(
        "mma.sync.aligned.m16n8k16.row.col.f32.bf16.bf16.f32 "
        "{%0,%1,%2,%3},{%4,%5,%6,%7},{%8,%9},{%0,%1,%2,%3};"
        : "+f"(d[0]), "+f"(d[1]), "+f"(d[2]), "+f"(d[3])
        : "r"(a[0]), "r"(a[1]), "r"(a[2]), "r"(a[3]), "r"(b0), "r"(b1));
}
// pack two f32 into bf16x2: low half = a, high half = b
__device__ __forceinline__ uint32_t bf2(float a, float b) {
    uint32_t r;
    asm("cvt.rn.bf16x2.f32 %0, %2, %1;" : "=r"(r) : "f"(a), "f"(b));
    return r;
}
__device__ __forceinline__ float ubf_lo(uint32_t r) { return __uint_as_float(r << 16); }
__device__ __forceinline__ float ubf_hi(uint32_t r) { return __uint_as_float(r & 0xffff0000u); }
__device__ __forceinline__ float ex2(float x) {
    float y; asm("ex2.approx.f32 %0, %1;" : "=f"(y) : "f"(x)); return y;
}

// ---------------------------------------------------------------------------
// Preprocessing: x -> bf16 hi/lo
// ---------------------------------------------------------------------------
__global__ __launch_bounds__(256) void convert_x_kernel(const float* __restrict__ x)
{
    int i = blockIdx.x * 256 + threadIdx.x;
    float4 v = ((const float4*)x)[i];
    uint32_t h0 = bf2(v.x, v.y), h1 = bf2(v.z, v.w);
    uint32_t l0 = bf2(v.x - ubf_lo(h0), v.y - ubf_hi(h0));
    uint32_t l1 = bf2(v.z - ubf_lo(h1), v.w - ubf_hi(h1));
    ((uint2*)g_xhi)[i] = make_uint2(h0, h1);
    ((uint2*)g_xlo)[i] = make_uint2(l0, l1);
}

// ---------------------------------------------------------------------------
// W [K,N] fp32 -> W^T [N,K] bf16 hi/lo.  SEL 0: qkv, 1: proj
// ---------------------------------------------------------------------------
template<int SEL>
__global__ __launch_bounds__(256) void transpose_w_kernel(const float* __restrict__ W, int N)
{
    __shared__ float tile[32][33];
    int tx = threadIdx.x, ty = threadIdx.y;          // (32, 8)
    int n0 = blockIdx.x * 32;
    int k0 = blockIdx.y * 32;
#pragma unroll
    for (int j = 0; j < 4; j++)
        tile[ty + j*8][tx] = W[(size_t)(k0 + ty + j*8) * N + n0 + tx];
    __syncthreads();
    __nv_bfloat16* Th = SEL ? g_wpT_hi : g_wqT_hi;
    __nv_bfloat16* Tl = SEL ? g_wpT_lo : g_wqT_lo;
#pragma unroll
    for (int j = 0; j < 4; j++) {
        float v = tile[tx][ty + j*8];
        __nv_bfloat16 h = __float2bfloat16(v);
        size_t o = (size_t)(n0 + ty + j*8) * KK + k0 + tx;
        Th[o] = h;
        Tl[o] = __float2bfloat16(v - __bfloat162float(h));
    }
}

// ---------------------------------------------------------------------------
// HMMA GEMM (same core as round 3).
// MODE 0: scatter output as bf16 hi/lo into g_q*/g_k*/g_v*.  MODE 1: fp32 out.
// ---------------------------------------------------------------------------
#define SUB_BYTES 10240        // 128 rows x 80B
#define STAGE_BYTES (4*SUB_BYTES)
#define GEMM_SMEM (2*STAGE_BYTES)   // 81920

template<int MODE>
__global__ __launch_bounds__(256, 2)
void gemm_tc(const float* __restrict__ bias, float* __restrict__ out)
{
    extern __shared__ char smem[];
    const uint32_t sbase = smem_u32(smem);

    const int tid = threadIdx.x;
    const int wid = tid >> 5;
    const int lane = tid & 31;
    const int wm = wid >> 2;
    const int wn = wid & 3;
    const int m0 = blockIdx.y * 128;
    const int n0 = blockIdx.x * 128;

    const __nv_bfloat16* Ahi = MODE ? g_atthi : g_xhi;
    const __nv_bfloat16* Alo = MODE ? g_attlo : g_xlo;
    const __nv_bfloat16* Bhi = MODE ? g_wpT_hi : g_wqT_hi;
    const __nv_bfloat16* Blo = MODE ? g_wpT_lo : g_wqT_lo;

    const __nv_bfloat16* gsrc[4] = {
        Ahi + (size_t)m0 * KK, Alo + (size_t)m0 * KK,
        Bhi + (size_t)n0 * KK, Blo + (size_t)n0 * KK };

    auto load_stage = [&](int s) {
        const int k0 = s * 32;
        const uint32_t sb = sbase + (s & 1) * STAGE_BYTES;
#pragma unroll
        for (int i = 0; i < 8; i++) {
            int id = i * 256 + tid;
            int sub = id >> 9;
            int row = (id & 511) >> 2;
            int c = id & 3;
            const void* src = gsrc[sub] + (size_t)row * KK + k0 + c * 8;
            cp16(sb + sub * SUB_BYTES + row * 80 + c * 16, src);
        }
        CP_COMMIT();
    };

    const uint32_t laneOff = (lane & 15) * 80 + (lane >> 4) * 16;

    float acc[4][4][4];
#pragma unroll
    for (int i = 0; i < 4; i++)
#pragma unroll
        for (int j = 0; j < 4; j++)
#pragma unroll
            for (int e = 0; e < 4; e++) acc[i][j][e] = 0.f;

    load_stage(0);

    for (int s = 0; s < 32; s++) {
        if (s + 1 < 32) { load_stage(s + 1); CP_WAIT(1); }
        else            { CP_WAIT(0); }
        __syncthreads();

        const uint32_t sb = sbase + (s & 1) * STAGE_BYTES;
        const uint32_t aB = sb + (wm * 64) * 80 + laneOff;
        const uint32_t bB = sb + 2 * SUB_BYTES + (wn * 32) * 80 + laneOff;

#pragma unroll
        for (int ks = 0; ks < 2; ks++) {
            const uint32_t ko = ks * 32;
            uint32_t af[16], bh[8], bl[8];
#pragma unroll
            for (int mi = 0; mi < 4; mi++) ldsm_x4(&af[mi*4], aB + mi * 16 * 80 + ko);
#pragma unroll
            for (int np = 0; np < 2; np++) ldsm_x4(&bh[np*4], bB + np * 16 * 80 + ko);
#pragma unroll
            for (int np = 0; np < 2; np++) ldsm_x4(&bl[np*4], bB + SUB_BYTES + np * 16 * 80 + ko);

#pragma unroll
            for (int mi = 0; mi < 4; mi++)
#pragma unroll
                for (int ni = 0; ni < 4; ni++) {
                    int np = ni >> 1, h = ni & 1;
                    mma_bf16(acc[mi][ni], &af[mi*4], bh[np*4+h], bh[np*4+2+h]);
                }
#pragma unroll
            for (int mi = 0; mi < 4; mi++)
#pragma unroll
                for (int ni = 0; ni < 4; ni++) {
                    int np = ni >> 1, h = ni & 1;
                    mma_bf16(acc[mi][ni], &af[mi*4], bl[np*4+h], bl[np*4+2+h]);
                }
#pragma unroll
            for (int mi = 0; mi < 4; mi++) ldsm_x4(&af[mi*4], aB + SUB_BYTES + mi * 16 * 80 + ko);
#pragma unroll
            for (int mi = 0; mi < 4; mi++)
#pragma unroll
                for (int ni = 0; ni < 4; ni++) {
                    int np = ni >> 1, h = ni & 1;
                    mma_bf16(acc[mi][ni], &af[mi*4], bh[np*4+h], bh[np*4+2+h]);
                }
        }
        __syncthreads();
    }

    float* Ssm = (float*)smem;          // [128][132]
#pragma unroll
    for (int mi = 0; mi < 4; mi++) {
        int m = wm * 64 + mi * 16 + (lane >> 2);
#pragma unroll
        for (int ni = 0; ni < 4; ni++) {
            int n = wn * 32 + ni * 8 + 2 * (lane & 3);
            Ssm[m * 132 + n]           = acc[mi][ni][0];
            Ssm[m * 132 + n + 1]       = acc[mi][ni][1];
            Ssm[(m + 8) * 132 + n]     = acc[mi][ni][2];
            Ssm[(m + 8) * 132 + n + 1] = acc[mi][ni][3];
        }
    }
    __syncthreads();

#pragma unroll 4
    for (int it = 0; it < 16; it++) {
        int f4 = it * 256 + tid;
        int row = f4 >> 5;
        int nl = (f4 & 31) * 4;
        float4 v = *(const float4*)&Ssm[row * 132 + nl];
        float4 bv = *(const float4*)&bias[n0 + nl];
        v.x += bv.x; v.y += bv.y; v.z += bv.z; v.w += bv.w;
        int gm = m0 + row;
        int gn = n0 + nl;
        if (MODE) {
            *(float4*)&out[(size_t)gm * CC + gn] = v;
        } else {
            int b = gm >> 10, t = gm & 1023;
            int sel = gn >> 10, c = gn & 1023;
            int h = c >> 6, d = c & 63;
            __nv_bfloat16* dh = (sel == 0) ? g_qhi : ((sel == 1) ? g_khi : g_vhi);
            __nv_bfloat16* dl = (sel == 0) ? g_qlo : ((sel == 1) ? g_klo : g_vlo);
            size_t idx = (((size_t)b * HH + h) * TT + t) * HS + d;
            uint32_t h0 = bf2(v.x, v.y), h1 = bf2(v.z, v.w);
            uint32_t l0 = bf2(v.x - ubf_lo(h0), v.y - ubf_hi(h0));
            uint32_t l1 = bf2(v.z - ubf_lo(h1), v.w - ubf_hi(h1));
            *(uint2*)&dh[idx] = make_uint2(h0, h1);
            *(uint2*)&dl[idx] = make_uint2(l0, l1);
        }
    }
}

// ---------------------------------------------------------------------------
// HMMA flash attention. 4 warps, q-tile 64 (16 rows/warp), kv-tile 64.
// S = 3-pass hi/lo QK^T; softmax fp32 (ex2, shfl); P,V hi/lo 3-pass PV.
// smem: Qhi/Qlo [64x72bf16] + 2 stages x (Khi,Klo,Vhi,Vlo)[64x72bf16]
// ---------------------------------------------------------------------------
#define ROWB 144                      // 72 bf16 row stride
#define ARR_B (64*ROWB)               // 9216
#define ATT_STG(s) (18432 + (s)*4*ARR_B)
#define ATT_SMEM (18432 + 2*4*ARR_B)  // 92160
#define SC_LOG2E 0.18033688011112042f // 0.125 * log2(e)

__global__ __launch_bounds__(128)
void attn_hmma_kernel()
{
    extern __shared__ char smem[];
    const uint32_t sb = smem_u32(smem);

    const int tid = threadIdx.x;
    const int w = tid >> 5;
    const int lane = tid & 31;
    const int qt = 15 - blockIdx.x;        // longest-first
    const int h = blockIdx.y;
    const int b = blockIdx.z;

    const size_t headoff = ((size_t)b * HH + h) * TT * HS;
    const __nv_bfloat16* Qh = g_qhi + headoff + (size_t)qt * 64 * HS;
    const __nv_bfloat16* Ql = g_qlo + headoff + (size_t)qt * 64 * HS;

    // --- issue Q + KV(0) loads ---
    {
        const __nv_bfloat16* qsrc[2] = { Qh, Ql };
#pragma unroll
        for (int i = 0; i < 8; i++) {
            int id = i * 128 + tid;
            int arr = id >> 9;
            int row = (id >> 3) & 63;
            int c = id & 7;
            cp16(sb + arr * ARR_B + row * ROWB + c * 16,
                 qsrc[arr] + (size_t)row * HS + c * 8);
        }
    }
    auto load_kv = [&](int jt) {
        const size_t kvoff = headoff + (size_t)jt * 64 * HS;
        const __nv_bfloat16* src[4] = { g_khi + kvoff, g_klo + kvoff,
                                        g_vhi + kvoff, g_vlo + kvoff };
        const uint32_t stg = sb + ATT_STG(jt & 1);
#pragma unroll
        for (int i = 0; i < 16; i++) {
            int id = i * 128 + tid;
            int arr = id >> 9;
            int row = (id >> 3) & 63;
            int c = id & 7;
            cp16(stg + arr * ARR_B + row * ROWB + c * 16,
                 src[arr] + (size_t)row * HS + c * 8);
        }
        CP_COMMIT();
    };
    load_kv(0);   // Q rides in this group too

    // fragment state
    uint32_t aQh[4][4], aQl[4][4];
    float o[8][4];
#pragma unroll
    for (int t = 0; t < 8; t++)
#pragma unroll
        for (int e = 0; e < 4; e++) o[t][e] = 0.f;
    float m0r = -INFINITY, m1r = -INFINITY, l0r = 0.f, l1r = 0.f;

    const uint32_t qlOff = (lane & 15) * ROWB + (lane >> 4) * 16;
    const int rloc = lane >> 2;            // row within 16 (and +8)
    const int cpair = 2 * (lane & 3);

    for (int jt = 0; jt <= qt; jt++) {
        if (jt < qt) { load_kv(jt + 1); CP_WAIT(1); }
        else         { CP_WAIT(0); }
        __syncthreads();

        if (jt == 0) {
            // load Q fragments once
            const uint32_t qb = sb + (w * 16) * ROWB + qlOff;
#pragma unroll
            for (int kd = 0; kd < 4; kd++) {
                ldsm_x4(aQh[kd], qb + kd * 32);
                ldsm_x4(aQl[kd], qb + ARR_B + kd * 32);
            }
        }

        const uint32_t stg = sb + ATT_STG(jt & 1);
        const uint32_t kb = stg + qlOff;   // K rows = kv index

        // ---- S = Q K^T (3 passes) ----
        float s[8][4];
#pragma unroll
        for (int t = 0; t < 8; t++)
#pragma unroll
            for (int e = 0; e < 4; e++) s[t][e] = 0.f;

#pragma unroll
        for (int kd = 0; kd < 4; kd++) {
            uint32_t kh[16], kl[16];
#pragma unroll
            for (int np = 0; np < 4; np++) {
                ldsm_x4(&kh[np*4], kb + np * 16 * ROWB + kd * 32);
                ldsm_x4(&kl[np*4], kb + ARR_B + np * 16 * ROWB + kd * 32);
            }
#pragma unroll
            for (int t = 0; t < 8; t++) {
                int np = t >> 1, hh = t & 1;
                mma_bf16(s[t], aQh[kd], kh[np*4+hh], kh[np*4+2+hh]);
                mma_bf16(s[t], aQh[kd], kl[np*4+hh], kl[np*4+2+hh]);
                mma_bf16(s[t], aQl[kd], kh[np*4+hh], kh[np*4+2+hh]);
            }
        }

        // ---- softmax (per-thread rows r0 = 16w+rloc, r1 = +8) ----
        const bool diag = (jt == qt);
#pragma unroll
        for (int q = 0; q < 2; q++) {
            float mold = q ? m1r : m0r;
            float mx = mold;
#pragma unroll
            for (int t = 0; t < 8; t++)
#pragma unroll
                for (int e = 0; e < 2; e++) {
                    float v = s[t][2*q+e] * SC_LOG2E;
                    if (diag && (8*t + cpair + e > 16*w + rloc + 8*q)) v = -INFINITY;
                    s[t][2*q+e] = v;
                    mx = fmaxf(mx, v);
                }
            mx = fmaxf(mx, __shfl_xor_sync(0xffffffffu, mx, 1));
            mx = fmaxf(mx, __shfl_xor_sync(0xffffffffu, mx, 2));
            float f = ex2(mold - mx);
            float sum = 0.f;
#pragma unroll
            for (int t = 0; t < 8; t++)
#pragma unroll
                for (int e = 0; e < 2; e++) {
                    float p = ex2(s[t][2*q+e] - mx);
                    s[t][2*q+e] = p;
                    sum += p;
                }
            sum += __shfl_xor_sync(0xffffffffu, sum, 1);
            sum += __shfl_xor_sync(0xffffffffu, sum, 2);
            if (q == 0) { l0r = l0r * f + sum; m0r = mx; }
            else        { l1r = l1r * f + sum; m1r = mx; }
#pragma unroll
            for (int t = 0; t < 8; t++) {
                o[t][2*q+0] *= f;
                o[t][2*q+1] *= f;
            }
        }

        // ---- O += P V (3 passes), P hi/lo from s frags ----
        const uint32_t vb = stg + 2 * ARR_B
                          + (((lane >> 3) & 1) * 8 + (lane & 7)) * ROWB
                          + (lane >> 4) * 16;
#pragma unroll
        for (int u = 0; u < 4; u++) {
            uint32_t aPh[4], aPl[4];
            {
                uint32_t r0 = bf2(s[2*u][0],   s[2*u][1]);
                uint32_t r1 = bf2(s[2*u][2],   s[2*u][3]);
                uint32_t r2 = bf2(s[2*u+1][0], s[2*u+1][1]);
                uint32_t r3 = bf2(s[2*u+1][2], s[2*u+1][3]);
                aPh[0] = r0; aPh[1] = r1; aPh[2] = r2; aPh[3] = r3;
                aPl[0] = bf2(s[2*u][0]   - ubf_lo(r0), s[2*u][1]   - ubf_hi(r0));
                aPl[1] = bf2(s[2*u][2]   - ubf_lo(r1), s[2*u][3]   - ubf_hi(r1));
                aPl[2] = bf2(s[2*u+1][0] - ubf_lo(r2), s[2*u+1][1] - ubf_hi(r2));
                aPl[3] = bf2(s[2*u+1][2] - ubf_lo(r3), s[2*u+1][3] - ubf_hi(r3));
            }
            uint32_t vh[16], vl[16];
#pragma unroll
            for (int dp = 0; dp < 4; dp++) {
                ldsm_x4t(&vh[dp*4], vb + u * 16 * ROWB + dp * 32);
                ldsm_x4t(&vl[dp*4], vb + ARR_B + u * 16 * ROWB + dp * 32);
            }
#pragma unroll
            for (int t = 0; t < 8; t++) {
                int dp = t >> 1, hh = t & 1;
                mma_bf16(o[t], aPh, vh[dp*4+2*hh], vh[dp*4+2*hh+1]);
                mma_bf16(o[t], aPh, vl[dp*4+2*hh], vl[dp*4+2*hh+1]);
                mma_bf16(o[t], aPl, vh[dp*4+2*hh], vh[dp*4+2*hh+1]);
            }
        }
        __syncthreads();
    }

    // ---- epilogue: O/l -> bf16 hi/lo into g_att* ----
    const float inv0 = 1.0f / l0r;
    const float inv1 = 1.0f / l1r;
    const int row0 = b * TT + qt * 64 + 16 * w + rloc;
    uint32_t* outh = (uint32_t*)g_atthi;
    uint32_t* outl = (uint32_t*)g_attlo;
#pragma unroll
    for (int t = 0; t < 8; t++) {
        int col = h * HS + 8 * t + cpair;
        {
            float f0 = o[t][0] * inv0, f1 = o[t][1] * inv0;
            uint32_t hi = bf2(f0, f1);
            uint32_t lo = bf2(f0 - ubf_lo(hi), f1 - ubf_hi(hi));
            size_t idx = ((size_t)row0 * CC + col) >> 1;
            outh[idx] = hi; outl[idx] = lo;
        }
        {
            float f0 = o[t][2] * inv1, f1 = o[t][3] * inv1;
            uint32_t hi = bf2(f0, f1);
            uint32_t lo = bf2(f0 - ubf_lo(hi), f1 - ubf_hi(hi));
            size_t idx = ((size_t)(row0 + 8) * CC + col) >> 1;
            outh[idx] = hi; outl[idx] = lo;
        }
    }
}

// ---------------------------------------------------------------------------
extern "C" void kernel_launch(void* const* d_in, const int* in_sizes, int n_in,
                              void* d_out, int out_size)
{
    (void)in_sizes; (void)n_in; (void)out_size;
    const float* x     = (const float*)d_in[0];
    const float* Wqkv  = (const float*)d_in[1];
    const float* bqkv  = (const float*)d_in[2];
    const float* Wproj = (const float*)d_in[3];
    const float* bproj = (const float*)d_in[4];
    float* out = (float*)d_out;

    cudaFuncSetAttribute(gemm_tc<0>, cudaFuncAttributeMaxDynamicSharedMemorySize, GEMM_SMEM);
    cudaFuncSetAttribute(gemm_tc<1>, cudaFuncAttributeMaxDynamicSharedMemorySize, GEMM_SMEM);
    cudaFuncSetAttribute(attn_hmma_kernel, cudaFuncAttributeMaxDynamicSharedMemorySize, ATT_SMEM);

    // preprocessing
    convert_x_kernel<<<(M_TOT * KK / 4) / 256, 256>>>(x);
    transpose_w_kernel<0><<<dim3(N_QKV / 32, KK / 32), dim3(32, 8)>>>(Wqkv, N_QKV);
    transpose_w_kernel<1><<<dim3(CC / 32, KK / 32), dim3(32, 8)>>>(Wproj, CC);

    // QKV GEMM -> q/k/v bf16 hi/lo
    gemm_tc<0><<<dim3(N_QKV / 128, M_TOT / 128), 256, GEMM_SMEM>>>(bqkv, nullptr);

    // HMMA causal flash attention -> g_att hi/lo
    attn_hmma_kernel<<<dim3(TT / 64, HH, BB), 128, ATT_SMEM>>>();

    // output projection
    gemm_tc<1><<<dim3(CC / 128, M_TOT / 128), 256, GEMM_SMEM>>>(bproj, out);
}

// round 5
// speedup vs baseline: 4.4336x; 1.4484x over previous
#include <cuda_runtime.h>
#include <cuda_fp16.h>
#include <math.h>
#include <stdint.h>

#define BB 8
#define TT 1024
#define CC 1024
#define HH 16
#define HS 64
#define M_TOT (BB*TT)      // 8192
#define KK 1024
#define N_QKV (3*CC)       // 3072

// ---------------------------------------------------------------------------
// Scratch (__device__ globals — allocation-guard safe)
// ---------------------------------------------------------------------------
__device__ __half g_xhi[(size_t)M_TOT*KK];
__device__ __half g_xlo[(size_t)M_TOT*KK];
__device__ __half g_wqT[(size_t)N_QKV*KK];
__device__ __half g_wpT[(size_t)CC*KK];
__device__ __half g_qhi[(size_t)BB*HH*TT*HS];
__device__ __half g_qlo[(size_t)BB*HH*TT*HS];
__device__ __half g_k[(size_t)BB*HH*TT*HS];
__device__ __half g_v[(size_t)BB*HH*TT*HS];
__device__ __half g_atthi[(size_t)M_TOT*CC];
__device__ __half g_attlo[(size_t)M_TOT*CC];

// ---------------------------------------------------------------------------
// helpers
// ---------------------------------------------------------------------------
__device__ __forceinline__ uint32_t smem_u32(const void* p) {
    uint32_t a;
    asm("{ .reg .u64 t; cvta.to.shared.u64 t, %1; cvt.u32.u64 %0, t; }" : "=r"(a) : "l"(p));
    return a;
}
__device__ __forceinline__ void cp16(uint32_t dst, const void* src) {
    asm volatile("cp.async.cg.shared.global [%0], [%1], 16;" :: "r"(dst), "l"(src));
}
#define CP_COMMIT() asm volatile("cp.async.commit_group;" ::: "memory")
#define CP_WAIT(n)  asm volatile("cp.async.wait_group %0;" :: "n"(n) : "memory")

__device__ __forceinline__ void ldsm_x4(uint32_t* r, uint32_t addr) {
    asm volatile("ldmatrix.sync.aligned.m8n8.x4.shared.b16 {%0,%1,%2,%3}, [%4];"
        : "=r"(r[0]), "=r"(r[1]), "=r"(r[2]), "=r"(r[3]) : "r"(addr));
}
__device__ __forceinline__ void ldsm_x4t(uint32_t* r, uint32_t addr) {
    asm volatile("ldmatrix.sync.aligned.m8n8.x4.trans.shared.b16 {%0,%1,%2,%3}, [%4];"
        : "=r"(r[0]), "=r"(r[1]), "=r"(r[2]), "=r"(r[3]) : "r"(addr));
}
__device__ __forceinline__ void mma_fp16(float* d, const uint32_t* a,
                                         uint32_t b0, uint32_t b1) {
    asm volatile(
        "mma.sync.aligned.m16n8k16.row.col.f32.f16.f16.f32 "
        "{%0,%1,%2,%3},{%4,%5,%6,%7},{%8,%9},{%0,%1,%2,%3};"
        : "+f"(d[0]), "+f"(d[1]), "+f"(d[2]), "+f"(d[3])
        : "r"(a[0]), "r"(a[1]), "r"(a[2]), "r"(a[3]), "r"(b0), "r"(b1));
}
// pack two f32 into f16x2: low half = a, high half = b
__device__ __forceinline__ uint32_t hf2(float a, float b) {
    uint32_t r;
    asm("cvt.rn.f16x2.f32 %0, %2, %1;" : "=r"(r) : "f"(a), "f"(b));
    return r;
}
__device__ __forceinline__ float uhf_lo(uint32_t r) {
    return __half2float(__ushort_as_half((unsigned short)(r & 0xffffu)));
}
__device__ __forceinline__ float uhf_hi(uint32_t r) {
    return __half2float(__ushort_as_half((unsigned short)(r >> 16)));
}
__device__ __forceinline__ float ex2(float x) {
    float y; asm("ex2.approx.f32 %0, %1;" : "=f"(y) : "f"(x)); return y;
}

// ---------------------------------------------------------------------------
// Preprocessing: x -> fp16 hi/lo
// ---------------------------------------------------------------------------
__global__ __launch_bounds__(256) void convert_x_kernel(const float* __restrict__ x)
{
    int i = blockIdx.x * 256 + threadIdx.x;
    float4 v = ((const float4*)x)[i];
    uint32_t h0 = hf2(v.x, v.y), h1 = hf2(v.z, v.w);
    uint32_t l0 = hf2(v.x - uhf_lo(h0), v.y - uhf_hi(h0));
    uint32_t l1 = hf2(v.z - uhf_lo(h1), v.w - uhf_hi(h1));
    ((uint2*)g_xhi)[i] = make_uint2(h0, h1);
    ((uint2*)g_xlo)[i] = make_uint2(l0, l1);
}

// ---------------------------------------------------------------------------
// W [K,N] fp32 -> W^T [N,K] fp16 (single).  SEL 0: qkv, 1: proj
// ---------------------------------------------------------------------------
template<int SEL>
__global__ __launch_bounds__(256) void transpose_w_kernel(const float* __restrict__ W, int N)
{
    __shared__ float tile[32][33];
    int tx = threadIdx.x, ty = threadIdx.y;          // (32, 8)
    int n0 = blockIdx.x * 32;
    int k0 = blockIdx.y * 32;
#pragma unroll
    for (int j = 0; j < 4; j++)
        tile[ty + j*8][tx] = W[(size_t)(k0 + ty + j*8) * N + n0 + tx];
    __syncthreads();
    __half* Th = SEL ? g_wpT : g_wqT;
#pragma unroll
    for (int j = 0; j < 4; j++) {
        float v = tile[tx][ty + j*8];
        Th[(size_t)(n0 + ty + j*8) * KK + k0 + tx] = __float2half_rn(v);
    }
}

// ---------------------------------------------------------------------------
// HMMA GEMM, fp16 2-pass: D = (Ahi + Alo) @ B + bias.
// 128x128 CTA tile, BK=32, 256 threads (8 warps 2x4), warp tile 64x32.
// MODE 0: scatter q (hi/lo) / k / v.  MODE 1: fp32 out.
// ---------------------------------------------------------------------------
#define SUB_BYTES 10240        // 128 rows x 80B (32 fp16 + 16B pad)
#define STAGE_BYTES (3*SUB_BYTES)   // Ahi, Alo, B
#define GEMM_SMEM 67584             // max(2*STAGE_BYTES=61440, epi 128*132*4)

template<int MODE>
__global__ __launch_bounds__(256, 2)
void gemm_tc(const float* __restrict__ bias, float* __restrict__ out)
{
    extern __shared__ char smem[];
    const uint32_t sbase = smem_u32(smem);

    const int tid = threadIdx.x;
    const int wid = tid >> 5;
    const int lane = tid & 31;
    const int wm = wid >> 2;
    const int wn = wid & 3;
    const int m0 = blockIdx.y * 128;
    const int n0 = blockIdx.x * 128;

    const __half* Ahi = MODE ? g_atthi : g_xhi;
    const __half* Alo = MODE ? g_attlo : g_xlo;
    const __half* Bw  = MODE ? g_wpT : g_wqT;

    const __half* gsrc[3] = {
        Ahi + (size_t)m0 * KK, Alo + (size_t)m0 * KK, Bw + (size_t)n0 * KK };

    // 1536 16B chunks per stage, 6 per thread
    auto load_stage = [&](int s) {
        const int k0 = s * 32;
        const uint32_t sb = sbase + (s & 1) * STAGE_BYTES;
#pragma unroll
        for (int i = 0; i < 6; i++) {
            int id = i * 256 + tid;
            int sub = id >> 9;
            int row = (id & 511) >> 2;
            int c = id & 3;
            const void* src = gsrc[sub] + (size_t)row * KK + k0 + c * 8;
            cp16(sb + sub * SUB_BYTES + row * 80 + c * 16, src);
        }
        CP_COMMIT();
    };

    const uint32_t laneOff = (lane & 15) * 80 + (lane >> 4) * 16;

    float acc[4][4][4];
#pragma unroll
    for (int i = 0; i < 4; i++)
#pragma unroll
        for (int j = 0; j < 4; j++)
#pragma unroll
            for (int e = 0; e < 4; e++) acc[i][j][e] = 0.f;

    load_stage(0);

    for (int s = 0; s < 32; s++) {
        if (s + 1 < 32) { load_stage(s + 1); CP_WAIT(1); }
        else            { CP_WAIT(0); }
        __syncthreads();

        const uint32_t sb = sbase + (s & 1) * STAGE_BYTES;
        const uint32_t aB = sb + (wm * 64) * 80 + laneOff;
        const uint32_t bB = sb + 2 * SUB_BYTES + (wn * 32) * 80 + laneOff;

#pragma unroll
        for (int ks = 0; ks < 2; ks++) {
            const uint32_t ko = ks * 32;
            uint32_t af[16], bh[8];
#pragma unroll
            for (int np = 0; np < 2; np++) ldsm_x4(&bh[np*4], bB + np * 16 * 80 + ko);
            // pass 1: Ahi * B
#pragma unroll
            for (int mi = 0; mi < 4; mi++) ldsm_x4(&af[mi*4], aB + mi * 16 * 80 + ko);
#pragma unroll
            for (int mi = 0; mi < 4; mi++)
#pragma unroll
                for (int ni = 0; ni < 4; ni++) {
                    int np = ni >> 1, h = ni & 1;
                    mma_fp16(acc[mi][ni], &af[mi*4], bh[np*4+h], bh[np*4+2+h]);
                }
            // pass 2: Alo * B
#pragma unroll
            for (int mi = 0; mi < 4; mi++) ldsm_x4(&af[mi*4], aB + SUB_BYTES + mi * 16 * 80 + ko);
#pragma unroll
            for (int mi = 0; mi < 4; mi++)
#pragma unroll
                for (int ni = 0; ni < 4; ni++) {
                    int np = ni >> 1, h = ni & 1;
                    mma_fp16(acc[mi][ni], &af[mi*4], bh[np*4+h], bh[np*4+2+h]);
                }
        }
        __syncthreads();
    }

    float* Ssm = (float*)smem;          // [128][132]
#pragma unroll
    for (int mi = 0; mi < 4; mi++) {
        int m = wm * 64 + mi * 16 + (lane >> 2);
#pragma unroll
        for (int ni = 0; ni < 4; ni++) {
            int n = wn * 32 + ni * 8 + 2 * (lane & 3);
            Ssm[m * 132 + n]           = acc[mi][ni][0];
            Ssm[m * 132 + n + 1]       = acc[mi][ni][1];
            Ssm[(m + 8) * 132 + n]     = acc[mi][ni][2];
            Ssm[(m + 8) * 132 + n + 1] = acc[mi][ni][3];
        }
    }
    __syncthreads();

#pragma unroll 4
    for (int it = 0; it < 16; it++) {
        int f4 = it * 256 + tid;
        int row = f4 >> 5;
        int nl = (f4 & 31) * 4;
        float4 v = *(const float4*)&Ssm[row * 132 + nl];
        float4 bv = *(const float4*)&bias[n0 + nl];
        v.x += bv.x; v.y += bv.y; v.z += bv.z; v.w += bv.w;
        int gm = m0 + row;
        int gn = n0 + nl;
        if (MODE) {
            *(float4*)&out[(size_t)gm * CC + gn] = v;
        } else {
            int b = gm >> 10, t = gm & 1023;
            int sel = gn >> 10, c = gn & 1023;
            int h = c >> 6, d = c & 63;
            size_t idx = (((size_t)b * HH + h) * TT + t) * HS + d;
            uint32_t h0 = hf2(v.x, v.y), h1 = hf2(v.z, v.w);
            if (sel == 0) {
                uint32_t l0 = hf2(v.x - uhf_lo(h0), v.y - uhf_hi(h0));
                uint32_t l1 = hf2(v.z - uhf_lo(h1), v.w - uhf_hi(h1));
                *(uint2*)&g_qhi[idx] = make_uint2(h0, h1);
                *(uint2*)&g_qlo[idx] = make_uint2(l0, l1);
            } else {
                __half* dst = (sel == 1) ? g_k : g_v;
                *(uint2*)&dst[idx] = make_uint2(h0, h1);
            }
        }
    }
}

// ---------------------------------------------------------------------------
// HMMA flash attention, fp16. 4 warps, q-tile 64, kv-tile 64.
// S = Qhi*K + Qlo*K (2-pass); softmax fp32; O += P*V (1-pass, P/V fp16).
// smem: Qhi,Qlo [64x(64+8)fp16] + 2 stages x (K,V)
// ---------------------------------------------------------------------------
#define ROWB 144                      // 72 fp16 row stride (bytes)
#define ARR_B (64*ROWB)               // 9216
#define ATT_STG(s) (2*ARR_B + (s)*2*ARR_B)
#define ATT_SMEM (6*ARR_B)            // 55296
#define SC_LOG2E 0.18033688011112042f // 0.125 * log2(e)

__global__ __launch_bounds__(128)
void attn_hmma_kernel()
{
    extern __shared__ char smem[];
    const uint32_t sb = smem_u32(smem);

    const int tid = threadIdx.x;
    const int w = tid >> 5;
    const int lane = tid & 31;
    const int qt = 15 - blockIdx.x;        // longest-first
    const int h = blockIdx.y;
    const int b = blockIdx.z;

    const size_t headoff = ((size_t)b * HH + h) * TT * HS;
    const __half* Qh = g_qhi + headoff + (size_t)qt * 64 * HS;
    const __half* Ql = g_qlo + headoff + (size_t)qt * 64 * HS;

    // --- issue Q loads (Qh @0, Ql @ARR_B) ---
    {
        const __half* qsrc[2] = { Qh, Ql };
#pragma unroll
        for (int i = 0; i < 8; i++) {
            int id = i * 128 + tid;
            int arr = id >> 9;
            int row = (id >> 3) & 63;
            int c = id & 7;
            cp16(sb + arr * ARR_B + row * ROWB + c * 16,
                 qsrc[arr] + (size_t)row * HS + c * 8);
        }
    }
    auto load_kv = [&](int jt) {
        const size_t kvoff = headoff + (size_t)jt * 64 * HS;
        const __half* src[2] = { g_k + kvoff, g_v + kvoff };
        const uint32_t stg = sb + ATT_STG(jt & 1);
#pragma unroll
        for (int i = 0; i < 8; i++) {
            int id = i * 128 + tid;
            int arr = id >> 9;
            int row = (id >> 3) & 63;
            int c = id & 7;
            cp16(stg + arr * ARR_B + row * ROWB + c * 16,
                 src[arr] + (size_t)row * HS + c * 8);
        }
        CP_COMMIT();
    };
    load_kv(0);   // Q rides in this group

    uint32_t aQh[4][4], aQl[4][4];
    float o[8][4];
#pragma unroll
    for (int t = 0; t < 8; t++)
#pragma unroll
        for (int e = 0; e < 4; e++) o[t][e] = 0.f;
    float m0r = -INFINITY, m1r = -INFINITY, l0r = 0.f, l1r = 0.f;

    const uint32_t qlOff = (lane & 15) * ROWB + (lane >> 4) * 16;
    const int rloc = lane >> 2;
    const int cpair = 2 * (lane & 3);

    for (int jt = 0; jt <= qt; jt++) {
        if (jt < qt) { load_kv(jt + 1); CP_WAIT(1); }
        else         { CP_WAIT(0); }
        __syncthreads();

        if (jt == 0) {
            const uint32_t qb = sb + (w * 16) * ROWB + qlOff;
#pragma unroll
            for (int kd = 0; kd < 4; kd++) {
                ldsm_x4(aQh[kd], qb + kd * 32);
                ldsm_x4(aQl[kd], qb + ARR_B + kd * 32);
            }
        }

        const uint32_t stg = sb + ATT_STG(jt & 1);
        const uint32_t kb = stg + qlOff;

        // ---- S = Q K^T (2 passes) ----
        float s[8][4];
#pragma unroll
        for (int t = 0; t < 8; t++)
#pragma unroll
            for (int e = 0; e < 4; e++) s[t][e] = 0.f;

#pragma unroll
        for (int kd = 0; kd < 4; kd++) {
            uint32_t kh[16];
#pragma unroll
            for (int np = 0; np < 4; np++)
                ldsm_x4(&kh[np*4], kb + np * 16 * ROWB + kd * 32);
#pragma unroll
            for (int t = 0; t < 8; t++) {
                int np = t >> 1, hh = t & 1;
                mma_fp16(s[t], aQh[kd], kh[np*4+hh], kh[np*4+2+hh]);
                mma_fp16(s[t], aQl[kd], kh[np*4+hh], kh[np*4+2+hh]);
            }
        }

        // ---- online softmax ----
        const bool diag = (jt == qt);
#pragma unroll
        for (int q = 0; q < 2; q++) {
            float mold = q ? m1r : m0r;
            float mx = mold;
#pragma unroll
            for (int t = 0; t < 8; t++)
#pragma unroll
                for (int e = 0; e < 2; e++) {
                    float v = s[t][2*q+e] * SC_LOG2E;
                    if (diag && (8*t + cpair + e > 16*w + rloc + 8*q)) v = -INFINITY;
                    s[t][2*q+e] = v;
                    mx = fmaxf(mx, v);
                }
            mx = fmaxf(mx, __shfl_xor_sync(0xffffffffu, mx, 1));
            mx = fmaxf(mx, __shfl_xor_sync(0xffffffffu, mx, 2));
            float f = ex2(mold - mx);
            float sum = 0.f;
#pragma unroll
            for (int t = 0; t < 8; t++)
#pragma unroll
                for (int e = 0; e < 2; e++) {
                    float p = ex2(s[t][2*q+e] - mx);
                    s[t][2*q+e] = p;
                    sum += p;
                }
            sum += __shfl_xor_sync(0xffffffffu, sum, 1);
            sum += __shfl_xor_sync(0xffffffffu, sum, 2);
            if (q == 0) { l0r = l0r * f + sum; m0r = mx; }
            else        { l1r = l1r * f + sum; m1r = mx; }
#pragma unroll
            for (int t = 0; t < 8; t++) {
                o[t][2*q+0] *= f;
                o[t][2*q+1] *= f;
            }
        }

        // ---- O += P V (1 pass) ----
        const uint32_t vb = stg + ARR_B
                          + (((lane >> 3) & 1) * 8 + (lane & 7)) * ROWB
                          + (lane >> 4) * 16;
#pragma unroll
        for (int u = 0; u < 4; u++) {
            uint32_t aP[4];
            aP[0] = hf2(s[2*u][0],   s[2*u][1]);
            aP[1] = hf2(s[2*u][2],   s[2*u][3]);
            aP[2] = hf2(s[2*u+1][0], s[2*u+1][1]);
            aP[3] = hf2(s[2*u+1][2], s[2*u+1][3]);
            uint32_t vh[16];
#pragma unroll
            for (int dp = 0; dp < 4; dp++)
                ldsm_x4t(&vh[dp*4], vb + u * 16 * ROWB + dp * 32);
#pragma unroll
            for (int t = 0; t < 8; t++) {
                int dp = t >> 1, hh = t & 1;
                mma_fp16(o[t], aP, vh[dp*4+2*hh], vh[dp*4+2*hh+1]);
            }
        }
        __syncthreads();
    }

    // ---- epilogue: O/l -> fp16 hi/lo into g_att* ----
    const float inv0 = 1.0f / l0r;
    const float inv1 = 1.0f / l1r;
    const int row0 = b * TT + qt * 64 + 16 * w + rloc;
    uint32_t* outh = (uint32_t*)g_atthi;
    uint32_t* outl = (uint32_t*)g_attlo;
#pragma unroll
    for (int t = 0; t < 8; t++) {
        int col = h * HS + 8 * t + cpair;
        {
            float f0 = o[t][0] * inv0, f1 = o[t][1] * inv0;
            uint32_t hi = hf2(f0, f1);
            uint32_t lo = hf2(f0 - uhf_lo(hi), f1 - uhf_hi(hi));
            size_t idx = ((size_t)row0 * CC + col) >> 1;
            outh[idx] = hi; outl[idx] = lo;
        }
        {
            float f0 = o[t][2] * inv1, f1 = o[t][3] * inv1;
            uint32_t hi = hf2(f0, f1);
            uint32_t lo = hf2(f0 - uhf_lo(hi), f1 - uhf_hi(hi));
            size_t idx = ((size_t)(row0 + 8) * CC + col) >> 1;
            outh[idx] = hi; outl[idx] = lo;
        }
    }
}

// ---------------------------------------------------------------------------
extern "C" void kernel_launch(void* const* d_in, const int* in_sizes, int n_in,
                              void* d_out, int out_size)
{
    (void)in_sizes; (void)n_in; (void)out_size;
    const float* x     = (const float*)d_in[0];
    const float* Wqkv  = (const float*)d_in[1];
    const float* bqkv  = (const float*)d_in[2];
    const float* Wproj = (const float*)d_in[3];
    const float* bproj = (const float*)d_in[4];
    float* out = (float*)d_out;

    cudaFuncSetAttribute(gemm_tc<0>, cudaFuncAttributeMaxDynamicSharedMemorySize, GEMM_SMEM);
    cudaFuncSetAttribute(gemm_tc<1>, cudaFuncAttributeMaxDynamicSharedMemorySize, GEMM_SMEM);
    cudaFuncSetAttribute(attn_hmma_kernel, cudaFuncAttributeMaxDynamicSharedMemorySize, ATT_SMEM);

    // preprocessing
    convert_x_kernel<<<(M_TOT * KK / 4) / 256, 256>>>(x);
    transpose_w_kernel<0><<<dim3(N_QKV / 32, KK / 32), dim3(32, 8)>>>(Wqkv, N_QKV);
    transpose_w_kernel<1><<<dim3(CC / 32, KK / 32), dim3(32, 8)>>>(Wproj, CC);

    // QKV GEMM (fp16 2-pass) -> q hi/lo, k, v
    gemm_tc<0><<<dim3(N_QKV / 128, M_TOT / 128), 256, GEMM_SMEM>>>(bqkv, nullptr);

    // HMMA causal flash attention -> att hi/lo
    attn_hmma_kernel<<<dim3(TT / 64, HH, BB), 128, ATT_SMEM>>>();

    // output projection (fp16 2-pass)
    gemm_tc<1><<<dim3(CC / 128, M_TOT / 128), 256, GEMM_SMEM>>>(bproj, out);
}

// round 6
// speedup vs baseline: 6.8211x; 1.5385x over previous
#include <cuda_runtime.h>
#include <cuda_fp16.h>
#include <math.h>
#include <stdint.h>

#define BB 8
#define TT 1024
#define CC 1024
#define HH 16
#define HS 64
#define M_TOT (BB*TT)      // 8192
#define KK 1024
#define N_QKV (3*CC)       // 3072

// ---------------------------------------------------------------------------
// Scratch (__device__ globals — allocation-guard safe)
// ---------------------------------------------------------------------------
__device__ __half g_x[(size_t)M_TOT*KK];
__device__ __half g_wqT[(size_t)N_QKV*KK];
__device__ __half g_wpT[(size_t)CC*KK];
__device__ __half g_qhi[(size_t)BB*HH*TT*HS];
__device__ __half g_qlo[(size_t)BB*HH*TT*HS];
__device__ __half g_k[(size_t)BB*HH*TT*HS];
__device__ __half g_v[(size_t)BB*HH*TT*HS];
__device__ __half g_att[(size_t)M_TOT*CC];

// ---------------------------------------------------------------------------
// helpers
// ---------------------------------------------------------------------------
__device__ __forceinline__ uint32_t smem_u32(const void* p) {
    uint32_t a;
    asm("{ .reg .u64 t; cvta.to.shared.u64 t, %1; cvt.u32.u64 %0, t; }" : "=r"(a) : "l"(p));
    return a;
}
__device__ __forceinline__ void cp16(uint32_t dst, const void* src) {
    asm volatile("cp.async.cg.shared.global [%0], [%1], 16;" :: "r"(dst), "l"(src));
}
#define CP_COMMIT() asm volatile("cp.async.commit_group;" ::: "memory")
#define CP_WAIT(n)  asm volatile("cp.async.wait_group %0;" :: "n"(n) : "memory")

__device__ __forceinline__ void ldsm_x4(uint32_t* r, uint32_t addr) {
    asm volatile("ldmatrix.sync.aligned.m8n8.x4.shared.b16 {%0,%1,%2,%3}, [%4];"
        : "=r"(r[0]), "=r"(r[1]), "=r"(r[2]), "=r"(r[3]) : "r"(addr));
}
__device__ __forceinline__ void ldsm_x4t(uint32_t* r, uint32_t addr) {
    asm volatile("ldmatrix.sync.aligned.m8n8.x4.trans.shared.b16 {%0,%1,%2,%3}, [%4];"
        : "=r"(r[0]), "=r"(r[1]), "=r"(r[2]), "=r"(r[3]) : "r"(addr));
}
__device__ __forceinline__ void mma_fp16(float* d, const uint32_t* a,
                                         uint32_t b0, uint32_t b1) {
    asm volatile(
        "mma.sync.aligned.m16n8k16.row.col.f32.f16.f16.f32 "
        "{%0,%1,%2,%3},{%4,%5,%6,%7},{%8,%9},{%0,%1,%2,%3};"
        : "+f"(d[0]), "+f"(d[1]), "+f"(d[2]), "+f"(d[3])
        : "r"(a[0]), "r"(a[1]), "r"(a[2]), "r"(a[3]), "r"(b0), "r"(b1));
}
__device__ __forceinline__ uint32_t hf2(float a, float b) {
    uint32_t r;
    asm("cvt.rn.f16x2.f32 %0, %2, %1;" : "=r"(r) : "f"(a), "f"(b));
    return r;
}
__device__ __forceinline__ float uhf_lo(uint32_t r) {
    return __half2float(__ushort_as_half((unsigned short)(r & 0xffffu)));
}
__device__ __forceinline__ float uhf_hi(uint32_t r) {
    return __half2float(__ushort_as_half((unsigned short)(r >> 16)));
}
__device__ __forceinline__ float ex2(float x) {
    float y; asm("ex2.approx.f32 %0, %1;" : "=f"(y) : "f"(x)); return y;
}

// ---------------------------------------------------------------------------
// Preprocessing: x -> fp16 (single)
// ---------------------------------------------------------------------------
__global__ __launch_bounds__(256) void convert_x_kernel(const float* __restrict__ x)
{
    int i = blockIdx.x * 256 + threadIdx.x;
    float4 v = ((const float4*)x)[i];
    ((uint2*)g_x)[i] = make_uint2(hf2(v.x, v.y), hf2(v.z, v.w));
}

// ---------------------------------------------------------------------------
// W [K,N] fp32 -> W^T [N,K] fp16.  SEL 0: qkv, 1: proj
// ---------------------------------------------------------------------------
template<int SEL>
__global__ __launch_bounds__(256) void transpose_w_kernel(const float* __restrict__ W, int N)
{
    __shared__ float tile[32][33];
    int tx = threadIdx.x, ty = threadIdx.y;          // (32, 8)
    int n0 = blockIdx.x * 32;
    int k0 = blockIdx.y * 32;
#pragma unroll
    for (int j = 0; j < 4; j++)
        tile[ty + j*8][tx] = W[(size_t)(k0 + ty + j*8) * N + n0 + tx];
    __syncthreads();
    __half* Th = SEL ? g_wpT : g_wqT;
#pragma unroll
    for (int j = 0; j < 4; j++) {
        float v = tile[tx][ty + j*8];
        Th[(size_t)(n0 + ty + j*8) * KK + k0 + tx] = __float2half_rn(v);
    }
}

// ---------------------------------------------------------------------------
// HMMA GEMM, fp16 1-pass: D = A @ B + bias. 128x128 CTA tile, BK=32,
// 256 threads (8 warps 2x4), warp tile 64x32, 3-stage cp.async ring.
// MODE 0: A=g_x, B=g_wqT, scatter q hi/lo + k + v.  MODE 1: A=g_att, fp32 out.
// ---------------------------------------------------------------------------
#define SUB_BYTES 10240             // 128 rows x 80B (32 fp16 + 16B pad)
#define STAGE_BYTES (2*SUB_BYTES)   // A, B
#define GEMM_SMEM 67584             // max(3*STAGE=61440, epi 128*132*4)

template<int MODE>
__global__ __launch_bounds__(256, 2)
void gemm_tc(const float* __restrict__ bias, float* __restrict__ out)
{
    extern __shared__ char smem[];
    const uint32_t sbase = smem_u32(smem);

    const int tid = threadIdx.x;
    const int wid = tid >> 5;
    const int lane = tid & 31;
    const int wm = wid >> 2;
    const int wn = wid & 3;
    const int m0 = blockIdx.y * 128;
    const int n0 = blockIdx.x * 128;

    const __half* Aw = MODE ? g_att : g_x;
    const __half* Bw = MODE ? g_wpT : g_wqT;
    const __half* gsrc[2] = { Aw + (size_t)m0 * KK, Bw + (size_t)n0 * KK };

    // 1024 16B chunks per stage, 4 per thread
    auto load_stage = [&](int s) {
        const int k0 = s * 32;
        const uint32_t sb = sbase + (s % 3) * STAGE_BYTES;
#pragma unroll
        for (int i = 0; i < 4; i++) {
            int id = i * 256 + tid;
            int sub = id >> 9;
            int row = (id & 511) >> 2;
            int c = id & 3;
            const void* src = gsrc[sub] + (size_t)row * KK + k0 + c * 8;
            cp16(sb + sub * SUB_BYTES + row * 80 + c * 16, src);
        }
        CP_COMMIT();
    };

    const uint32_t laneOff = (lane & 15) * 80 + (lane >> 4) * 16;

    float acc[4][4][4];
#pragma unroll
    for (int i = 0; i < 4; i++)
#pragma unroll
        for (int j = 0; j < 4; j++)
#pragma unroll
            for (int e = 0; e < 4; e++) acc[i][j][e] = 0.f;

    load_stage(0);
    load_stage(1);

    for (int s = 0; s < 32; s++) {
        CP_WAIT(1);
        __syncthreads();
        if (s + 2 < 32) load_stage(s + 2);

        const uint32_t sb = sbase + (s % 3) * STAGE_BYTES;
        const uint32_t aB = sb + (wm * 64) * 80 + laneOff;
        const uint32_t bB = sb + SUB_BYTES + (wn * 32) * 80 + laneOff;

#pragma unroll
        for (int ks = 0; ks < 2; ks++) {
            const uint32_t ko = ks * 32;
            uint32_t af[16], bh[8];
#pragma unroll
            for (int np = 0; np < 2; np++) ldsm_x4(&bh[np*4], bB + np * 16 * 80 + ko);
#pragma unroll
            for (int mi = 0; mi < 4; mi++) ldsm_x4(&af[mi*4], aB + mi * 16 * 80 + ko);
#pragma unroll
            for (int mi = 0; mi < 4; mi++)
#pragma unroll
                for (int ni = 0; ni < 4; ni++) {
                    int np = ni >> 1, h = ni & 1;
                    mma_fp16(acc[mi][ni], &af[mi*4], bh[np*4+h], bh[np*4+2+h]);
                }
        }
    }
    __syncthreads();

    float* Ssm = (float*)smem;          // [128][132]
#pragma unroll
    for (int mi = 0; mi < 4; mi++) {
        int m = wm * 64 + mi * 16 + (lane >> 2);
#pragma unroll
        for (int ni = 0; ni < 4; ni++) {
            int n = wn * 32 + ni * 8 + 2 * (lane & 3);
            Ssm[m * 132 + n]           = acc[mi][ni][0];
            Ssm[m * 132 + n + 1]       = acc[mi][ni][1];
            Ssm[(m + 8) * 132 + n]     = acc[mi][ni][2];
            Ssm[(m + 8) * 132 + n + 1] = acc[mi][ni][3];
        }
    }
    __syncthreads();

#pragma unroll 4
    for (int it = 0; it < 16; it++) {
        int f4 = it * 256 + tid;
        int row = f4 >> 5;
        int nl = (f4 & 31) * 4;
        float4 v = *(const float4*)&Ssm[row * 132 + nl];
        float4 bv = *(const float4*)&bias[n0 + nl];
        v.x += bv.x; v.y += bv.y; v.z += bv.z; v.w += bv.w;
        int gm = m0 + row;
        int gn = n0 + nl;
        if (MODE) {
            *(float4*)&out[(size_t)gm * CC + gn] = v;
        } else {
            int b = gm >> 10, t = gm & 1023;
            int sel = gn >> 10, c = gn & 1023;
            int h = c >> 6, d = c & 63;
            size_t idx = (((size_t)b * HH + h) * TT + t) * HS + d;
            uint32_t h0 = hf2(v.x, v.y), h1 = hf2(v.z, v.w);
            if (sel == 0) {
                uint32_t l0 = hf2(v.x - uhf_lo(h0), v.y - uhf_hi(h0));
                uint32_t l1 = hf2(v.z - uhf_lo(h1), v.w - uhf_hi(h1));
                *(uint2*)&g_qhi[idx] = make_uint2(h0, h1);
                *(uint2*)&g_qlo[idx] = make_uint2(l0, l1);
            } else {
                __half* dst = (sel == 1) ? g_k : g_v;
                *(uint2*)&dst[idx] = make_uint2(h0, h1);
            }
        }
    }
}

// ---------------------------------------------------------------------------
// HMMA flash attention, fp16. 4 warps, q-tile 64, kv-tile 64.
// S = Qhi*K + Qlo*K (2-pass); softmax fp32; O += P*V (1-pass).
// Output: g_att single fp16.
// ---------------------------------------------------------------------------
#define ROWB 144                      // 72 fp16 row stride (bytes)
#define ARR_B (64*ROWB)               // 9216
#define ATT_STG(s) (2*ARR_B + (s)*2*ARR_B)
#define ATT_SMEM (6*ARR_B)            // 55296
#define SC_LOG2E 0.18033688011112042f // 0.125 * log2(e)

__global__ __launch_bounds__(128)
void attn_hmma_kernel()
{
    extern __shared__ char smem[];
    const uint32_t sb = smem_u32(smem);

    const int tid = threadIdx.x;
    const int w = tid >> 5;
    const int lane = tid & 31;
    const int qt = 15 - blockIdx.x;        // longest-first
    const int h = blockIdx.y;
    const int b = blockIdx.z;

    const size_t headoff = ((size_t)b * HH + h) * TT * HS;
    const __half* Qh = g_qhi + headoff + (size_t)qt * 64 * HS;
    const __half* Ql = g_qlo + headoff + (size_t)qt * 64 * HS;

    {
        const __half* qsrc[2] = { Qh, Ql };
#pragma unroll
        for (int i = 0; i < 8; i++) {
            int id = i * 128 + tid;
            int arr = id >> 9;
            int row = (id >> 3) & 63;
            int c = id & 7;
            cp16(sb + arr * ARR_B + row * ROWB + c * 16,
                 qsrc[arr] + (size_t)row * HS + c * 8);
        }
    }
    auto load_kv = [&](int jt) {
        const size_t kvoff = headoff + (size_t)jt * 64 * HS;
        const __half* src[2] = { g_k + kvoff, g_v + kvoff };
        const uint32_t stg = sb + ATT_STG(jt & 1);
#pragma unroll
        for (int i = 0; i < 8; i++) {
            int id = i * 128 + tid;
            int arr = id >> 9;
            int row = (id >> 3) & 63;
            int c = id & 7;
            cp16(stg + arr * ARR_B + row * ROWB + c * 16,
                 src[arr] + (size_t)row * HS + c * 8);
        }
        CP_COMMIT();
    };
    load_kv(0);   // Q rides in this group

    uint32_t aQh[4][4], aQl[4][4];
    float o[8][4];
#pragma unroll
    for (int t = 0; t < 8; t++)
#pragma unroll
        for (int e = 0; e < 4; e++) o[t][e] = 0.f;
    float m0r = -INFINITY, m1r = -INFINITY, l0r = 0.f, l1r = 0.f;

    const uint32_t qlOff = (lane & 15) * ROWB + (lane >> 4) * 16;
    const int rloc = lane >> 2;
    const int cpair = 2 * (lane & 3);

    for (int jt = 0; jt <= qt; jt++) {
        if (jt < qt) { load_kv(jt + 1); CP_WAIT(1); }
        else         { CP_WAIT(0); }
        __syncthreads();

        if (jt == 0) {
            const uint32_t qb = sb + (w * 16) * ROWB + qlOff;
#pragma unroll
            for (int kd = 0; kd < 4; kd++) {
                ldsm_x4(aQh[kd], qb + kd * 32);
                ldsm_x4(aQl[kd], qb + ARR_B + kd * 32);
            }
        }

        const uint32_t stg = sb + ATT_STG(jt & 1);
        const uint32_t kb = stg + qlOff;

        float s[8][4];
#pragma unroll
        for (int t = 0; t < 8; t++)
#pragma unroll
            for (int e = 0; e < 4; e++) s[t][e] = 0.f;

#pragma unroll
        for (int kd = 0; kd < 4; kd++) {
            uint32_t kh[16];
#pragma unroll
            for (int np = 0; np < 4; np++)
                ldsm_x4(&kh[np*4], kb + np * 16 * ROWB + kd * 32);
#pragma unroll
            for (int t = 0; t < 8; t++) {
                int np = t >> 1, hh = t & 1;
                mma_fp16(s[t], aQh[kd], kh[np*4+hh], kh[np*4+2+hh]);
                mma_fp16(s[t], aQl[kd], kh[np*4+hh], kh[np*4+2+hh]);
            }
        }

        const bool diag = (jt == qt);
#pragma unroll
        for (int q = 0; q < 2; q++) {
            float mold = q ? m1r : m0r;
            float mx = mold;
#pragma unroll
            for (int t = 0; t < 8; t++)
#pragma unroll
                for (int e = 0; e < 2; e++) {
                    float v = s[t][2*q+e] * SC_LOG2E;
                    if (diag && (8*t + cpair + e > 16*w + rloc + 8*q)) v = -INFINITY;
                    s[t][2*q+e] = v;
                    mx = fmaxf(mx, v);
                }
            mx = fmaxf(mx, __shfl_xor_sync(0xffffffffu, mx, 1));
            mx = fmaxf(mx, __shfl_xor_sync(0xffffffffu, mx, 2));
            float f = ex2(mold - mx);
            float sum = 0.f;
#pragma unroll
            for (int t = 0; t < 8; t++)
#pragma unroll
                for (int e = 0; e < 2; e++) {
                    float p = ex2(s[t][2*q+e] - mx);
                    s[t][2*q+e] = p;
                    sum += p;
                }
            sum += __shfl_xor_sync(0xffffffffu, sum, 1);
            sum += __shfl_xor_sync(0xffffffffu, sum, 2);
            if (q == 0) { l0r = l0r * f + sum; m0r = mx; }
            else        { l1r = l1r * f + sum; m1r = mx; }
#pragma unroll
            for (int t = 0; t < 8; t++) {
                o[t][2*q+0] *= f;
                o[t][2*q+1] *= f;
            }
        }

        const uint32_t vb = stg + ARR_B
                          + (((lane >> 3) & 1) * 8 + (lane & 7)) * ROWB
                          + (lane >> 4) * 16;
#pragma unroll
        for (int u = 0; u < 4; u++) {
            uint32_t aP[4];
            aP[0] = hf2(s[2*u][0],   s[2*u][1]);
            aP[1] = hf2(s[2*u][2],   s[2*u][3]);
            aP[2] = hf2(s[2*u+1][0], s[2*u+1][1]);
            aP[3] = hf2(s[2*u+1][2], s[2*u+1][3]);
            uint32_t vh[16];
#pragma unroll
            for (int dp = 0; dp < 4; dp++)
                ldsm_x4t(&vh[dp*4], vb + u * 16 * ROWB + dp * 32);
#pragma unroll
            for (int t = 0; t < 8; t++) {
                int dp = t >> 1, hh = t & 1;
                mma_fp16(o[t], aP, vh[dp*4+2*hh], vh[dp*4+2*hh+1]);
            }
        }
        __syncthreads();
    }

    // ---- epilogue: O/l -> fp16 into g_att ----
    const float inv0 = 1.0f / l0r;
    const float inv1 = 1.0f / l1r;
    const int row0 = b * TT + qt * 64 + 16 * w + rloc;
    uint32_t* outp = (uint32_t*)g_att;
#pragma unroll
    for (int t = 0; t < 8; t++) {
        int col = h * HS + 8 * t + cpair;
        outp[((size_t)row0 * CC + col) >> 1]       = hf2(o[t][0] * inv0, o[t][1] * inv0);
        outp[((size_t)(row0 + 8) * CC + col) >> 1] = hf2(o[t][2] * inv1, o[t][3] * inv1);
    }
}

// ---------------------------------------------------------------------------
extern "C" void kernel_launch(void* const* d_in, const int* in_sizes, int n_in,
                              void* d_out, int out_size)
{
    (void)in_sizes; (void)n_in; (void)out_size;
    const float* x     = (const float*)d_in[0];
    const float* Wqkv  = (const float*)d_in[1];
    const float* bqkv  = (const float*)d_in[2];
    const float* Wproj = (const float*)d_in[3];
    const float* bproj = (const float*)d_in[4];
    float* out = (float*)d_out;

    cudaFuncSetAttribute(gemm_tc<0>, cudaFuncAttributeMaxDynamicSharedMemorySize, GEMM_SMEM);
    cudaFuncSetAttribute(gemm_tc<1>, cudaFuncAttributeMaxDynamicSharedMemorySize, GEMM_SMEM);
    cudaFuncSetAttribute(attn_hmma_kernel, cudaFuncAttributeMaxDynamicSharedMemorySize, ATT_SMEM);

    // preprocessing
    convert_x_kernel<<<(M_TOT * KK / 4) / 256, 256>>>(x);
    transpose_w_kernel<0><<<dim3(N_QKV / 32, KK / 32), dim3(32, 8)>>>(Wqkv, N_QKV);
    transpose_w_kernel<1><<<dim3(CC / 32, KK / 32), dim3(32, 8)>>>(Wproj, CC);

    // QKV GEMM (fp16 1-pass) -> q hi/lo, k, v
    gemm_tc<0><<<dim3(N_QKV / 128, M_TOT / 128), 256, GEMM_SMEM>>>(bqkv, nullptr);

    // HMMA causal flash attention -> g_att fp16
    attn_hmma_kernel<<<dim3(TT / 64, HH, BB), 128, ATT_SMEM>>>();

    // output projection (fp16 1-pass)
    gemm_tc<1><<<dim3(CC / 128, M_TOT / 128), 256, GEMM_SMEM>>>(bproj, out);
}

// round 7
// speedup vs baseline: 9.0236x; 1.3229x over previous
#include <cuda_runtime.h>
#include <cuda_fp16.h>
#include <math.h>
#include <stdint.h>

#define BB 8
#define TT 1024
#define CC 1024
#define HH 16
#define HS 64
#define M_TOT (BB*TT)      // 8192
#define KK 1024
#define N_QKV (3*CC)       // 3072

// ---------------------------------------------------------------------------
// Scratch (__device__ globals — allocation-guard safe)
// ---------------------------------------------------------------------------
__device__ __half g_x[(size_t)M_TOT*KK];
__device__ __half g_wq[(size_t)KK*N_QKV];   // [K,N] native layout
__device__ __half g_wp[(size_t)KK*CC];      // [K,N]
__device__ __half g_qhi[(size_t)BB*HH*TT*HS];
__device__ __half g_qlo[(size_t)BB*HH*TT*HS];
__device__ __half g_k[(size_t)BB*HH*TT*HS];
__device__ __half g_v[(size_t)BB*HH*TT*HS];
__device__ __half g_att[(size_t)M_TOT*CC];

// ---------------------------------------------------------------------------
// helpers
// ---------------------------------------------------------------------------
__device__ __forceinline__ uint32_t smem_u32(const void* p) {
    uint32_t a;
    asm("{ .reg .u64 t; cvta.to.shared.u64 t, %1; cvt.u32.u64 %0, t; }" : "=r"(a) : "l"(p));
    return a;
}
__device__ __forceinline__ void cp16(uint32_t dst, const void* src) {
    asm volatile("cp.async.cg.shared.global [%0], [%1], 16;" :: "r"(dst), "l"(src));
}
#define CP_COMMIT() asm volatile("cp.async.commit_group;" ::: "memory")
#define CP_WAIT(n)  asm volatile("cp.async.wait_group %0;" :: "n"(n) : "memory")

__device__ __forceinline__ void ldsm_x4(uint32_t* r, uint32_t addr) {
    asm volatile("ldmatrix.sync.aligned.m8n8.x4.shared.b16 {%0,%1,%2,%3}, [%4];"
        : "=r"(r[0]), "=r"(r[1]), "=r"(r[2]), "=r"(r[3]) : "r"(addr));
}
__device__ __forceinline__ void ldsm_x4t(uint32_t* r, uint32_t addr) {
    asm volatile("ldmatrix.sync.aligned.m8n8.x4.trans.shared.b16 {%0,%1,%2,%3}, [%4];"
        : "=r"(r[0]), "=r"(r[1]), "=r"(r[2]), "=r"(r[3]) : "r"(addr));
}
__device__ __forceinline__ void mma_fp16(float* d, const uint32_t* a,
                                         uint32_t b0, uint32_t b1) {
    asm volatile(
        "mma.sync.aligned.m16n8k16.row.col.f32.f16.f16.f32 "
        "{%0,%1,%2,%3},{%4,%5,%6,%7},{%8,%9},{%0,%1,%2,%3};"
        : "+f"(d[0]), "+f"(d[1]), "+f"(d[2]), "+f"(d[3])
        : "r"(a[0]), "r"(a[1]), "r"(a[2]), "r"(a[3]), "r"(b0), "r"(b1));
}
__device__ __forceinline__ uint32_t hf2(float a, float b) {
    uint32_t r;
    asm("cvt.rn.f16x2.f32 %0, %2, %1;" : "=r"(r) : "f"(a), "f"(b));
    return r;
}
__device__ __forceinline__ float uhf_lo(uint32_t r) {
    return __half2float(__ushort_as_half((unsigned short)(r & 0xffffu)));
}
__device__ __forceinline__ float uhf_hi(uint32_t r) {
    return __half2float(__ushort_as_half((unsigned short)(r >> 16)));
}
__device__ __forceinline__ float ex2(float x) {
    float y; asm("ex2.approx.f32 %0, %1;" : "=f"(y) : "f"(x)); return y;
}

// ---------------------------------------------------------------------------
// Preprocessing: elementwise fp32 -> fp16 (no transpose)
// ---------------------------------------------------------------------------
__global__ __launch_bounds__(256) void convert_x_kernel(const float* __restrict__ x)
{
    int i = blockIdx.x * 256 + threadIdx.x;
    float4 v = ((const float4*)x)[i];
    ((uint2*)g_x)[i] = make_uint2(hf2(v.x, v.y), hf2(v.z, v.w));
}
template<int SEL>
__global__ __launch_bounds__(256) void convert_w_kernel(const float* __restrict__ W)
{
    int i = blockIdx.x * 256 + threadIdx.x;
    float4 v = ((const float4*)W)[i];
    __half* T = SEL ? g_wp : g_wq;
    ((uint2*)T)[i] = make_uint2(hf2(v.x, v.y), hf2(v.z, v.w));
}

// ---------------------------------------------------------------------------
// HMMA GEMM, fp16 1-pass: D = A @ B + bias.
// A [M,K] row-major (k-contig, non-trans ldsm); B [K,N] row-major (trans ldsm).
// CTA 128x128, BK=64, 256 threads (8 warps 2x4), warp tile 64x32, 3-stage ring.
// XOR-swizzled smem, no padding.
// MODE 0: A=g_x, B=g_wq, scatter q hi/lo + k + v.  MODE 1: A=g_att, fp32 out.
// ---------------------------------------------------------------------------
#define A_BYTES 16384               // 128 rows x 128B (64 fp16)
#define STAGE_BYTES 32768           // + B: 64 rows x 256B (128 fp16)
#define GEMM_SMEM 98304             // 3 stages (epilogue 128*132*4=67584 fits)

template<int MODE>
__global__ __launch_bounds__(256, 2)
void gemm_tc(const float* __restrict__ bias, float* __restrict__ out)
{
    extern __shared__ char smem[];
    const uint32_t sbase = smem_u32(smem);

    const int tid = threadIdx.x;
    const int wid = tid >> 5;
    const int lane = tid & 31;
    const int wm = wid >> 2;          // 0..1
    const int wn = wid & 3;           // 0..3
    const int m0 = blockIdx.y * 128;
    const int n0 = blockIdx.x * 128;
    const int N = MODE ? CC : N_QKV;

    const __half* Ap = (MODE ? g_att : g_x) + (size_t)m0 * KK;
    const __half* Bp = (MODE ? g_wp : g_wq) + n0;

    auto load_stage = [&](int s) {
        const int k0 = s * 64;
        const uint32_t sb = sbase + (s % 3) * STAGE_BYTES;
        // A: 1024 chunks (row k-contig), 4/thread
#pragma unroll
        for (int i = 0; i < 4; i++) {
            int id = i * 256 + tid;
            int row = id >> 3;
            int c = id & 7;
            cp16(sb + row * 128 + (((uint32_t)c << 4) ^ ((row & 7) << 4)),
                 Ap + (size_t)row * KK + k0 + c * 8);
        }
        // B: 1024 chunks (row = k, n-contig), 4/thread
#pragma unroll
        for (int i = 0; i < 4; i++) {
            int id = i * 256 + tid;
            int row = id >> 4;
            int c = id & 15;
            cp16(sb + A_BYTES + row * 256 + (((uint32_t)c << 4) ^ ((row & 7) << 4)),
                 Bp + (size_t)(k0 + row) * N + c * 8);
        }
        CP_COMMIT();
    };

    float acc[4][4][4];
#pragma unroll
    for (int i = 0; i < 4; i++)
#pragma unroll
        for (int j = 0; j < 4; j++)
#pragma unroll
            for (int e = 0; e < 4; e++) acc[i][j][e] = 0.f;

    load_stage(0);
    load_stage(1);

    for (int s = 0; s < 16; s++) {
        if (s + 1 < 16) CP_WAIT(1); else CP_WAIT(0);
        __syncthreads();
        if (s + 2 < 16) load_stage(s + 2);

        const uint32_t sb = sbase + (s % 3) * STAGE_BYTES;

#pragma unroll
        for (int ks = 0; ks < 4; ks++) {
            uint32_t af[16], bt[8];
            // A frags: m16k16 per ldsm.x4, rows m, chunk = ks*2 + (lane>>4)
            {
                int arow0 = wm * 64 + (lane & 15);
                int cA = ks * 2 + (lane >> 4);
#pragma unroll
                for (int mi = 0; mi < 4; mi++) {
                    int row = arow0 + mi * 16;
                    ldsm_x4(&af[mi*4],
                            sb + row * 128 + (((uint32_t)cA << 4) ^ ((row & 7) << 4)));
                }
            }
            // B frags: trans ldsm, rows = k, 16 n per x4
            {
                int brow = ks * 16 + ((lane >> 3) & 1) * 8 + (lane & 7);
#pragma unroll
                for (int np = 0; np < 2; np++) {
                    int cb = wn * 4 + np * 2 + (lane >> 4);
                    ldsm_x4t(&bt[np*4],
                             sb + A_BYTES + brow * 256 +
                             (((uint32_t)cb << 4) ^ ((brow & 7) << 4)));
                }
            }
#pragma unroll
            for (int mi = 0; mi < 4; mi++)
#pragma unroll
                for (int ni = 0; ni < 4; ni++) {
                    int np = ni >> 1, hh = ni & 1;
                    mma_fp16(acc[mi][ni], &af[mi*4], bt[np*4+2*hh], bt[np*4+2*hh+1]);
                }
        }
    }
    __syncthreads();

    // ---- epilogue: accums -> smem fp32, then coalesced stores ----
    float* Ssm = (float*)smem;          // [128][132]
#pragma unroll
    for (int mi = 0; mi < 4; mi++) {
        int m = wm * 64 + mi * 16 + (lane >> 2);
#pragma unroll
        for (int ni = 0; ni < 4; ni++) {
            int n = wn * 32 + ni * 8 + 2 * (lane & 3);
            Ssm[m * 132 + n]           = acc[mi][ni][0];
            Ssm[m * 132 + n + 1]       = acc[mi][ni][1];
            Ssm[(m + 8) * 132 + n]     = acc[mi][ni][2];
            Ssm[(m + 8) * 132 + n + 1] = acc[mi][ni][3];
        }
    }
    __syncthreads();

#pragma unroll 4
    for (int it = 0; it < 16; it++) {
        int f4 = it * 256 + tid;
        int row = f4 >> 5;
        int nl = (f4 & 31) * 4;
        float4 v = *(const float4*)&Ssm[row * 132 + nl];
        float4 bv = *(const float4*)&bias[n0 + nl];
        v.x += bv.x; v.y += bv.y; v.z += bv.z; v.w += bv.w;
        int gm = m0 + row;
        int gn = n0 + nl;
        if (MODE) {
            *(float4*)&out[(size_t)gm * CC + gn] = v;
        } else {
            int b = gm >> 10, t = gm & 1023;
            int sel = gn >> 10, c = gn & 1023;
            int h = c >> 6, d = c & 63;
            size_t idx = (((size_t)b * HH + h) * TT + t) * HS + d;
            uint32_t h0 = hf2(v.x, v.y), h1 = hf2(v.z, v.w);
            if (sel == 0) {
                uint32_t l0 = hf2(v.x - uhf_lo(h0), v.y - uhf_hi(h0));
                uint32_t l1 = hf2(v.z - uhf_lo(h1), v.w - uhf_hi(h1));
                *(uint2*)&g_qhi[idx] = make_uint2(h0, h1);
                *(uint2*)&g_qlo[idx] = make_uint2(l0, l1);
            } else {
                __half* dst = (sel == 1) ? g_k : g_v;
                *(uint2*)&dst[idx] = make_uint2(h0, h1);
            }
        }
    }
}

// ---------------------------------------------------------------------------
// HMMA flash attention, fp16 (unchanged from round 6).
// ---------------------------------------------------------------------------
#define ROWB 144
#define ARR_B (64*ROWB)
#define ATT_STG(s) (2*ARR_B + (s)*2*ARR_B)
#define ATT_SMEM (6*ARR_B)            // 55296
#define SC_LOG2E 0.18033688011112042f

__global__ __launch_bounds__(128)
void attn_hmma_kernel()
{
    extern __shared__ char smem[];
    const uint32_t sb = smem_u32(smem);

    const int tid = threadIdx.x;
    const int w = tid >> 5;
    const int lane = tid & 31;
    const int qt = 15 - blockIdx.x;
    const int h = blockIdx.y;
    const int b = blockIdx.z;

    const size_t headoff = ((size_t)b * HH + h) * TT * HS;
    const __half* Qh = g_qhi + headoff + (size_t)qt * 64 * HS;
    const __half* Ql = g_qlo + headoff + (size_t)qt * 64 * HS;

    {
        const __half* qsrc[2] = { Qh, Ql };
#pragma unroll
        for (int i = 0; i < 8; i++) {
            int id = i * 128 + tid;
            int arr = id >> 9;
            int row = (id >> 3) & 63;
            int c = id & 7;
            cp16(sb + arr * ARR_B + row * ROWB + c * 16,
                 qsrc[arr] + (size_t)row * HS + c * 8);
        }
    }
    auto load_kv = [&](int jt) {
        const size_t kvoff = headoff + (size_t)jt * 64 * HS;
        const __half* src[2] = { g_k + kvoff, g_v + kvoff };
        const uint32_t stg = sb + ATT_STG(jt & 1);
#pragma unroll
        for (int i = 0; i < 8; i++) {
            int id = i * 128 + tid;
            int arr = id >> 9;
            int row = (id >> 3) & 63;
            int c = id & 7;
            cp16(stg + arr * ARR_B + row * ROWB + c * 16,
                 src[arr] + (size_t)row * HS + c * 8);
        }
        CP_COMMIT();
    };
    load_kv(0);

    uint32_t aQh[4][4], aQl[4][4];
    float o[8][4];
#pragma unroll
    for (int t = 0; t < 8; t++)
#pragma unroll
        for (int e = 0; e < 4; e++) o[t][e] = 0.f;
    float m0r = -INFINITY, m1r = -INFINITY, l0r = 0.f, l1r = 0.f;

    const uint32_t qlOff = (lane & 15) * ROWB + (lane >> 4) * 16;
    const int rloc = lane >> 2;
    const int cpair = 2 * (lane & 3);

    for (int jt = 0; jt <= qt; jt++) {
        if (jt < qt) { load_kv(jt + 1); CP_WAIT(1); }
        else         { CP_WAIT(0); }
        __syncthreads();

        if (jt == 0) {
            const uint32_t qb = sb + (w * 16) * ROWB + qlOff;
#pragma unroll
            for (int kd = 0; kd < 4; kd++) {
                ldsm_x4(aQh[kd], qb + kd * 32);
                ldsm_x4(aQl[kd], qb + ARR_B + kd * 32);
            }
        }

        const uint32_t stg = sb + ATT_STG(jt & 1);
        const uint32_t kb = stg + qlOff;

        float s[8][4];
#pragma unroll
        for (int t = 0; t < 8; t++)
#pragma unroll
            for (int e = 0; e < 4; e++) s[t][e] = 0.f;

#pragma unroll
        for (int kd = 0; kd < 4; kd++) {
            uint32_t kh[16];
#pragma unroll
            for (int np = 0; np < 4; np++)
                ldsm_x4(&kh[np*4], kb + np * 16 * ROWB + kd * 32);
#pragma unroll
            for (int t = 0; t < 8; t++) {
                int np = t >> 1, hh = t & 1;
                mma_fp16(s[t], aQh[kd], kh[np*4+hh], kh[np*4+2+hh]);
                mma_fp16(s[t], aQl[kd], kh[np*4+hh], kh[np*4+2+hh]);
            }
        }

        const bool diag = (jt == qt);
#pragma unroll
        for (int q = 0; q < 2; q++) {
            float mold = q ? m1r : m0r;
            float mx = mold;
#pragma unroll
            for (int t = 0; t < 8; t++)
#pragma unroll
                for (int e = 0; e < 2; e++) {
                    float v = s[t][2*q+e] * SC_LOG2E;
                    if (diag && (8*t + cpair + e > 16*w + rloc + 8*q)) v = -INFINITY;
                    s[t][2*q+e] = v;
                    mx = fmaxf(mx, v);
                }
            mx = fmaxf(mx, __shfl_xor_sync(0xffffffffu, mx, 1));
            mx = fmaxf(mx, __shfl_xor_sync(0xffffffffu, mx, 2));
            float f = ex2(mold - mx);
            float sum = 0.f;
#pragma unroll
            for (int t = 0; t < 8; t++)
#pragma unroll
                for (int e = 0; e < 2; e++) {
                    float p = ex2(s[t][2*q+e] - mx);
                    s[t][2*q+e] = p;
                    sum += p;
                }
            sum += __shfl_xor_sync(0xffffffffu, sum, 1);
            sum += __shfl_xor_sync(0xffffffffu, sum, 2);
            if (q == 0) { l0r = l0r * f + sum; m0r = mx; }
            else        { l1r = l1r * f + sum; m1r = mx; }
#pragma unroll
            for (int t = 0; t < 8; t++) {
                o[t][2*q+0] *= f;
                o[t][2*q+1] *= f;
            }
        }

        const uint32_t vb = stg + ARR_B
                          + (((lane >> 3) & 1) * 8 + (lane & 7)) * ROWB
                          + (lane >> 4) * 16;
#pragma unroll
        for (int u = 0; u < 4; u++) {
            uint32_t aP[4];
            aP[0] = hf2(s[2*u][0],   s[2*u][1]);
            aP[1] = hf2(s[2*u][2],   s[2*u][3]);
            aP[2] = hf2(s[2*u+1][0], s[2*u+1][1]);
            aP[3] = hf2(s[2*u+1][2], s[2*u+1][3]);
            uint32_t vh[16];
#pragma unroll
            for (int dp = 0; dp < 4; dp++)
                ldsm_x4t(&vh[dp*4], vb + u * 16 * ROWB + dp * 32);
#pragma unroll
            for (int t = 0; t < 8; t++) {
                int dp = t >> 1, hh = t & 1;
                mma_fp16(o[t], aP, vh[dp*4+2*hh], vh[dp*4+2*hh+1]);
            }
        }
        __syncthreads();
    }

    const float inv0 = 1.0f / l0r;
    const float inv1 = 1.0f / l1r;
    const int row0 = b * TT + qt * 64 + 16 * w + rloc;
    uint32_t* outp = (uint32_t*)g_att;
#pragma unroll
    for (int t = 0; t < 8; t++) {
        int col = h * HS + 8 * t + cpair;
        outp[((size_t)row0 * CC + col) >> 1]       = hf2(o[t][0] * inv0, o[t][1] * inv0);
        outp[((size_t)(row0 + 8) * CC + col) >> 1] = hf2(o[t][2] * inv1, o[t][3] * inv1);
    }
}

// ---------------------------------------------------------------------------
extern "C" void kernel_launch(void* const* d_in, const int* in_sizes, int n_in,
                              void* d_out, int out_size)
{
    (void)in_sizes; (void)n_in; (void)out_size;
    const float* x     = (const float*)d_in[0];
    const float* Wqkv  = (const float*)d_in[1];
    const float* bqkv  = (const float*)d_in[2];
    const float* Wproj = (const float*)d_in[3];
    const float* bproj = (const float*)d_in[4];
    float* out = (float*)d_out;

    cudaFuncSetAttribute(gemm_tc<0>, cudaFuncAttributeMaxDynamicSharedMemorySize, GEMM_SMEM);
    cudaFuncSetAttribute(gemm_tc<1>, cudaFuncAttributeMaxDynamicSharedMemorySize, GEMM_SMEM);
    cudaFuncSetAttribute(attn_hmma_kernel, cudaFuncAttributeMaxDynamicSharedMemorySize, ATT_SMEM);

    // preprocessing (all elementwise now)
    convert_x_kernel<<<(M_TOT * KK / 4) / 256, 256>>>(x);
    convert_w_kernel<0><<<((size_t)KK * N_QKV / 4) / 256, 256>>>(Wqkv);
    convert_w_kernel<1><<<((size_t)KK * CC / 4) / 256, 256>>>(Wproj);

    // QKV GEMM (fp16 1-pass, BK=64) -> q hi/lo, k, v
    gemm_tc<0><<<dim3(N_QKV / 128, M_TOT / 128), 256, GEMM_SMEM>>>(bqkv, nullptr);

    // HMMA causal flash attention -> g_att fp16
    attn_hmma_kernel<<<dim3(TT / 64, HH, BB), 128, ATT_SMEM>>>();

    // output projection (fp16 1-pass, BK=64)
    gemm_tc<1><<<dim3(CC / 128, M_TOT / 128), 256, GEMM_SMEM>>>(bproj, out);
}